// round 1
// baseline (speedup 1.0000x reference)
#include <cuda_runtime.h>
#include <math.h>

#define N_B 4
#define T_S 4096
#define DIN 1024
#define D_E 128
#define NT (N_B * T_S)

// ---- scratch (device globals: allocation-free) ----
__device__ float g_q[NT * D_E];
__device__ float g_k[NT * D_E];
__device__ float g_v[NT * D_E];
__device__ float g_rowmax[NT];
__device__ float g_rowsum[NT];
__device__ float g_out_fallback[NT * D_E];

__device__ __forceinline__ float neg_inf() { return __int_as_float(0xff800000); }

// ============================================================
// K1: QKV projection. Y[w] = x @ W[w], w in {q,k,v}
// x: [NT, DIN] row-major, W: [DIN, D] row-major, out: [NT, D]
// 128x128 tile, BK=8, 256 threads, 8x8 microtile.
// ============================================================
__global__ __launch_bounds__(256) void qkv_gemm_kernel(
    const float* __restrict__ x,
    const float* __restrict__ Wq,
    const float* __restrict__ Wk,
    const float* __restrict__ Wv)
{
    const float* W = (blockIdx.y == 0) ? Wq : ((blockIdx.y == 1) ? Wk : Wv);
    float* out = (blockIdx.y == 0) ? g_q : ((blockIdx.y == 1) ? g_k : g_v);

    __shared__ float As[8][128];  // [k][m]
    __shared__ float Bs[8][128];  // [k][n]

    int tid = threadIdx.x;
    int tx = tid & 15, ty = tid >> 4;
    int aRow = tid >> 1, aCol = (tid & 1) * 4;
    int bRow = tid >> 5, bCol = (tid & 31) * 4;
    long mBase = (long)blockIdx.x * 128;

    float acc[8][8];
#pragma unroll
    for (int i = 0; i < 8; i++)
#pragma unroll
        for (int j = 0; j < 8; j++) acc[i][j] = 0.f;

    for (int k0 = 0; k0 < DIN; k0 += 8) {
        float4 a = *(const float4*)&x[(mBase + aRow) * DIN + k0 + aCol];
        As[aCol + 0][aRow] = a.x;
        As[aCol + 1][aRow] = a.y;
        As[aCol + 2][aRow] = a.z;
        As[aCol + 3][aRow] = a.w;
        *(float4*)&Bs[bRow][bCol] = *(const float4*)&W[(long)(k0 + bRow) * D_E + bCol];
        __syncthreads();
#pragma unroll
        for (int k = 0; k < 8; k++) {
            float ar[8], br[8];
#pragma unroll
            for (int i = 0; i < 8; i++) ar[i] = As[k][ty * 8 + i];
#pragma unroll
            for (int j = 0; j < 8; j++) br[j] = Bs[k][tx * 8 + j];
#pragma unroll
            for (int i = 0; i < 8; i++)
#pragma unroll
                for (int j = 0; j < 8; j++) acc[i][j] = fmaf(ar[i], br[j], acc[i][j]);
        }
        __syncthreads();
    }
#pragma unroll
    for (int i = 0; i < 8; i++) {
        long r = mBase + ty * 8 + i;
#pragma unroll
        for (int j = 0; j < 8; j += 4) {
            float4 v4 = make_float4(acc[i][j], acc[i][j + 1], acc[i][j + 2], acc[i][j + 3]);
            *(float4*)&out[r * D_E + tx * 8 + j] = v4;
        }
    }
}

// ============================================================
// K2: S = Q K^T, lower-triangular 128x128 tiles only.
// Writes raw logits into att[n][t][s] for s<=t, with the faithful
// quirk: logit == 0.0 -> -inf. Upper-tri left untouched (K4 zero-fills).
// ============================================================
__global__ __launch_bounds__(256) void scores_kernel(float* __restrict__ att)
{
    int tri = blockIdx.x;
    int n = blockIdx.y;
    // decode lower-tri (i,j), i >= j
    int i = (int)((sqrtf(8.f * tri + 1.f) - 1.f) * 0.5f);
    while ((i + 1) * (i + 2) / 2 <= tri) i++;
    while (i * (i + 1) / 2 > tri) i--;
    int j = tri - i * (i + 1) / 2;

    const float* Q = g_q + (long)n * T_S * D_E;
    const float* K = g_k + (long)n * T_S * D_E;
    float* attn = att + (long)n * T_S * T_S;

    __shared__ float As[8][128];
    __shared__ float Bs[8][128];

    int tid = threadIdx.x;
    int tx = tid & 15, ty = tid >> 4;
    int aRow = tid >> 1, aCol = (tid & 1) * 4;

    float acc[8][8];
#pragma unroll
    for (int a = 0; a < 8; a++)
#pragma unroll
        for (int b = 0; b < 8; b++) acc[a][b] = 0.f;

    for (int k0 = 0; k0 < D_E; k0 += 8) {
        float4 a = *(const float4*)&Q[(long)(i * 128 + aRow) * D_E + k0 + aCol];
        As[aCol + 0][aRow] = a.x;
        As[aCol + 1][aRow] = a.y;
        As[aCol + 2][aRow] = a.z;
        As[aCol + 3][aRow] = a.w;
        float4 b = *(const float4*)&K[(long)(j * 128 + aRow) * D_E + k0 + aCol];
        Bs[aCol + 0][aRow] = b.x;
        Bs[aCol + 1][aRow] = b.y;
        Bs[aCol + 2][aRow] = b.z;
        Bs[aCol + 3][aRow] = b.w;
        __syncthreads();
#pragma unroll
        for (int k = 0; k < 8; k++) {
            float ar[8], br[8];
#pragma unroll
            for (int a = 0; a < 8; a++) ar[a] = As[k][ty * 8 + a];
#pragma unroll
            for (int b = 0; b < 8; b++) br[b] = Bs[k][tx * 8 + b];
#pragma unroll
            for (int a = 0; a < 8; a++)
#pragma unroll
                for (int b = 0; b < 8; b++) acc[a][b] = fmaf(ar[a], br[b], acc[a][b]);
        }
        __syncthreads();
    }

#pragma unroll
    for (int a = 0; a < 8; a++) {
        int t = i * 128 + ty * 8 + a;
#pragma unroll
        for (int b = 0; b < 8; b++) {
            int s = j * 128 + tx * 8 + b;
            if (s <= t) {
                float v = acc[a][b];
                attn[(long)t * T_S + s] = (v == 0.0f) ? neg_inf() : v;
            }
        }
    }
}

// ============================================================
// K3: per-row softmax stats. One warp per row, coalesced reads.
// ============================================================
__global__ void softmax_stats_kernel(const float* __restrict__ att)
{
    int warp = (blockIdx.x * blockDim.x + threadIdx.x) >> 5;
    int lane = threadIdx.x & 31;
    if (warp >= NT) return;
    int n = warp / T_S, t = warp % T_S;
    const float* row = att + (long)n * T_S * T_S + (long)t * T_S;
    int len = t + 1;

    float m = neg_inf();
    for (int c = lane; c < len; c += 32) m = fmaxf(m, row[c]);
#pragma unroll
    for (int o = 16; o; o >>= 1) m = fmaxf(m, __shfl_xor_sync(0xffffffffu, m, o));

    float s = 0.f;
    for (int c = lane; c < len; c += 32) s += __expf(row[c] - m);
#pragma unroll
    for (int o = 16; o; o >>= 1) s += __shfl_xor_sync(0xffffffffu, s, o);

    if (lane == 0) {
        g_rowmax[warp] = m;
        g_rowsum[warp] = s;
    }
}

// ============================================================
// K4: out = softmax(S) @ V.  Computes p = exp(l - max)/sum while
// loading the A tile, writes normalized att back in place,
// zero-fills above the diagonal, accumulates out[128,128].
// ============================================================
__global__ __launch_bounds__(256) void pv_kernel(float* __restrict__ att,
                                                 float* __restrict__ out)
{
    int i = blockIdx.x;  // row tile
    int n = blockIdx.y;
    float* attn = att + (long)n * T_S * T_S;
    const float* V = g_v + (long)n * T_S * D_E;

    __shared__ float As[8][128];
    __shared__ float Bs[8][128];
    __shared__ float s_max[128], s_inv[128];

    int tid = threadIdx.x;
    if (tid < 128) {
        int r = n * T_S + i * 128 + tid;
        s_max[tid] = g_rowmax[r];
        s_inv[tid] = 1.f / g_rowsum[r];
    }
    __syncthreads();

    int tx = tid & 15, ty = tid >> 4;
    int aRow = tid >> 1, aCol = (tid & 1) * 4;
    int bRow = tid >> 5, bCol = (tid & 31) * 4;
    int tGlob = i * 128 + aRow;
    float rmax = s_max[aRow];
    float rinv = s_inv[aRow];

    float acc[8][8];
#pragma unroll
    for (int a = 0; a < 8; a++)
#pragma unroll
        for (int b = 0; b < 8; b++) acc[a][b] = 0.f;

    int kEnd = (i + 1) * 128;
    for (int k0 = 0; k0 < kEnd; k0 += 8) {
        int s0 = k0 + aCol;
        float4 a = *(const float4*)&attn[(long)tGlob * T_S + s0];
        float p0 = (s0 + 0 <= tGlob) ? __expf(a.x - rmax) * rinv : 0.f;
        float p1 = (s0 + 1 <= tGlob) ? __expf(a.y - rmax) * rinv : 0.f;
        float p2 = (s0 + 2 <= tGlob) ? __expf(a.z - rmax) * rinv : 0.f;
        float p3 = (s0 + 3 <= tGlob) ? __expf(a.w - rmax) * rinv : 0.f;
        As[aCol + 0][aRow] = p0;
        As[aCol + 1][aRow] = p1;
        As[aCol + 2][aRow] = p2;
        As[aCol + 3][aRow] = p3;
        *(float4*)&attn[(long)tGlob * T_S + s0] = make_float4(p0, p1, p2, p3);
        *(float4*)&Bs[bRow][bCol] = *(const float4*)&V[(long)(k0 + bRow) * D_E + bCol];
        __syncthreads();
#pragma unroll
        for (int k = 0; k < 8; k++) {
            float ar[8], br[8];
#pragma unroll
            for (int a2 = 0; a2 < 8; a2++) ar[a2] = As[k][ty * 8 + a2];
#pragma unroll
            for (int b2 = 0; b2 < 8; b2++) br[b2] = Bs[k][tx * 8 + b2];
#pragma unroll
            for (int a2 = 0; a2 < 8; a2++)
#pragma unroll
                for (int b2 = 0; b2 < 8; b2++) acc[a2][b2] = fmaf(ar[a2], br[b2], acc[a2][b2]);
        }
        __syncthreads();
    }

    // zero-fill att columns [kEnd, T)
    int zstart = kEnd;
    int Wd = T_S - zstart;
    if (Wd > 0) {
        long Z = (long)128 * Wd;
        float4 z = make_float4(0.f, 0.f, 0.f, 0.f);
        for (long e = (long)tid * 4; e < Z; e += 1024) {
            int row = (int)(e / Wd);
            int col = (int)(e % Wd);
            *(float4*)&attn[(long)(i * 128 + row) * T_S + zstart + col] = z;
        }
    }

    // write out tile
#pragma unroll
    for (int a = 0; a < 8; a++) {
        long r = (long)n * T_S + i * 128 + ty * 8 + a;
#pragma unroll
        for (int b = 0; b < 8; b += 4) {
            float4 v4 = make_float4(acc[a][b], acc[a][b + 1], acc[a][b + 2], acc[a][b + 3]);
            *(float4*)&out[r * D_E + tx * 8 + b] = v4;
        }
    }
}

// ============================================================
extern "C" void kernel_launch(void* const* d_in, const int* in_sizes, int n_in,
                              void* d_out, int out_size)
{
    const float* x  = (const float*)d_in[0];
    const float* Wq = (const float*)d_in[1];
    const float* Wk = (const float*)d_in[2];
    const float* Wv = (const float*)d_in[3];

    const long NTD = (long)NT * D_E;              // 2,097,152
    const long NTT = (long)N_B * T_S * T_S;       // 67,108,864

    float* dout = (float*)d_out;
    float* out_ptr;
    float* att_ptr;
    if ((long)out_size >= NTD + NTT) {
        out_ptr = dout;            // tuple (out, att) concatenated
        att_ptr = dout + NTD;
    } else if ((long)out_size == NTT) {
        att_ptr = dout;            // att only; out goes to scratch
        void* fb = nullptr;
        cudaGetSymbolAddress(&fb, g_out_fallback);
        out_ptr = (float*)fb;
    } else {
        out_ptr = dout;            // best effort
        att_ptr = dout;
    }

    qkv_gemm_kernel<<<dim3(NT / 128, 3), 256>>>(x, Wq, Wk, Wv);

    int nTiles = T_S / 128;                        // 32
    int nTri = nTiles * (nTiles + 1) / 2;          // 528
    scores_kernel<<<dim3(nTri, N_B), 256>>>(att_ptr);

    softmax_stats_kernel<<<NT / 8, 256>>>(att_ptr);

    pv_kernel<<<dim3(T_S / 128, N_B), 256>>>(att_ptr, out_ptr);
}

// round 2
// speedup vs baseline: 1.7031x; 1.7031x over previous
#include <cuda_runtime.h>
#include <math.h>

#define N_B 4
#define T_S 4096
#define DIN 1024
#define D_E 128
#define NT (N_B * T_S)

// ---- scratch (device globals: allocation-free) ----
__device__ float g_q[NT * D_E];
__device__ float g_k[NT * D_E];
__device__ float g_v[NT * D_E];
__device__ float g_rowmax[NT];
__device__ float g_rowsum[NT];
// split-K partials: [n][i-8][jg][128*128], i in 8..31, jg<4  -> 25 MB
__device__ float g_part[(long)4 * 24 * 4 * 128 * 128];
__device__ float g_out_fallback[NT * D_E];

__device__ __forceinline__ float neg_inf() { return __int_as_float(0xff800000); }

// ============================================================
// K1: QKV projection, double-buffered 128x128x8 SGEMM
// ============================================================
__global__ __launch_bounds__(256, 2) void qkv_gemm_kernel(
    const float* __restrict__ x,
    const float* __restrict__ Wq,
    const float* __restrict__ Wk,
    const float* __restrict__ Wv)
{
    const float* W = (blockIdx.y == 0) ? Wq : ((blockIdx.y == 1) ? Wk : Wv);
    float* out = (blockIdx.y == 0) ? g_q : ((blockIdx.y == 1) ? g_k : g_v);

    __shared__ float As[2][8][128];
    __shared__ float Bs[2][8][128];

    int tid = threadIdx.x;
    int tx = tid & 15, ty = tid >> 4;
    int aRow = tid >> 1, aCol = (tid & 1) * 4;
    int bRow = tid >> 5, bCol = (tid & 31) * 4;
    long mBase = (long)blockIdx.x * 128;
    const float* xrow = x + (mBase + aRow) * DIN;

    // initial tile
    {
        float4 a = *(const float4*)&xrow[aCol];
        As[0][aCol + 0][aRow] = a.x;
        As[0][aCol + 1][aRow] = a.y;
        As[0][aCol + 2][aRow] = a.z;
        As[0][aCol + 3][aRow] = a.w;
        *(float4*)&Bs[0][bRow][bCol] = *(const float4*)&W[(long)bRow * D_E + bCol];
    }
    __syncthreads();

    float acc[8][8];
#pragma unroll
    for (int i = 0; i < 8; i++)
#pragma unroll
        for (int j = 0; j < 8; j++) acc[i][j] = 0.f;

    int buf = 0;
    for (int k0 = 0; k0 < DIN; k0 += 8) {
        float4 na, nb;
        bool more = (k0 + 8 < DIN);
        if (more) {
            na = *(const float4*)&xrow[k0 + 8 + aCol];
            nb = *(const float4*)&W[(long)(k0 + 8 + bRow) * D_E + bCol];
        }
#pragma unroll
        for (int k = 0; k < 8; k++) {
            float ar[8], br[8];
#pragma unroll
            for (int i = 0; i < 8; i++) ar[i] = As[buf][k][ty * 8 + i];
#pragma unroll
            for (int j = 0; j < 8; j++) br[j] = Bs[buf][k][tx * 8 + j];
#pragma unroll
            for (int i = 0; i < 8; i++)
#pragma unroll
                for (int j = 0; j < 8; j++) acc[i][j] = fmaf(ar[i], br[j], acc[i][j]);
        }
        if (more) {
            As[buf ^ 1][aCol + 0][aRow] = na.x;
            As[buf ^ 1][aCol + 1][aRow] = na.y;
            As[buf ^ 1][aCol + 2][aRow] = na.z;
            As[buf ^ 1][aCol + 3][aRow] = na.w;
            *(float4*)&Bs[buf ^ 1][bRow][bCol] = nb;
        }
        __syncthreads();
        buf ^= 1;
    }
#pragma unroll
    for (int i = 0; i < 8; i++) {
        long r = mBase + ty * 8 + i;
#pragma unroll
        for (int j = 0; j < 8; j += 4) {
            float4 v4 = make_float4(acc[i][j], acc[i][j + 1], acc[i][j + 2], acc[i][j + 3]);
            *(float4*)&out[r * D_E + tx * 8 + j] = v4;
        }
    }
}

// ============================================================
// K2: S = Q K^T, lower-tri tiles, raw logits + (==0 -> -inf) quirk.
// ============================================================
__global__ __launch_bounds__(256, 2) void scores_kernel(float* __restrict__ att)
{
    int tri = blockIdx.x;
    int n = blockIdx.y;
    int i = (int)((sqrtf(8.f * tri + 1.f) - 1.f) * 0.5f);
    while ((i + 1) * (i + 2) / 2 <= tri) i++;
    while (i * (i + 1) / 2 > tri) i--;
    int j = tri - i * (i + 1) / 2;

    const float* Q = g_q + (long)n * T_S * D_E;
    const float* K = g_k + (long)n * T_S * D_E;
    float* attn = att + (long)n * T_S * T_S;

    __shared__ float As[2][8][128];
    __shared__ float Bs[2][8][128];

    int tid = threadIdx.x;
    int tx = tid & 15, ty = tid >> 4;
    int aRow = tid >> 1, aCol = (tid & 1) * 4;
    const float* qrow = Q + (long)(i * 128 + aRow) * D_E;
    const float* krow = K + (long)(j * 128 + aRow) * D_E;

    {
        float4 a = *(const float4*)&qrow[aCol];
        As[0][aCol + 0][aRow] = a.x;
        As[0][aCol + 1][aRow] = a.y;
        As[0][aCol + 2][aRow] = a.z;
        As[0][aCol + 3][aRow] = a.w;
        float4 b = *(const float4*)&krow[aCol];
        Bs[0][aCol + 0][aRow] = b.x;
        Bs[0][aCol + 1][aRow] = b.y;
        Bs[0][aCol + 2][aRow] = b.z;
        Bs[0][aCol + 3][aRow] = b.w;
    }
    __syncthreads();

    float acc[8][8];
#pragma unroll
    for (int a = 0; a < 8; a++)
#pragma unroll
        for (int b = 0; b < 8; b++) acc[a][b] = 0.f;

    int buf = 0;
    for (int k0 = 0; k0 < D_E; k0 += 8) {
        float4 na, nb;
        bool more = (k0 + 8 < D_E);
        if (more) {
            na = *(const float4*)&qrow[k0 + 8 + aCol];
            nb = *(const float4*)&krow[k0 + 8 + aCol];
        }
#pragma unroll
        for (int k = 0; k < 8; k++) {
            float ar[8], br[8];
#pragma unroll
            for (int a = 0; a < 8; a++) ar[a] = As[buf][k][ty * 8 + a];
#pragma unroll
            for (int b = 0; b < 8; b++) br[b] = Bs[buf][k][tx * 8 + b];
#pragma unroll
            for (int a = 0; a < 8; a++)
#pragma unroll
                for (int b = 0; b < 8; b++) acc[a][b] = fmaf(ar[a], br[b], acc[a][b]);
        }
        if (more) {
            As[buf ^ 1][aCol + 0][aRow] = na.x;
            As[buf ^ 1][aCol + 1][aRow] = na.y;
            As[buf ^ 1][aCol + 2][aRow] = na.z;
            As[buf ^ 1][aCol + 3][aRow] = na.w;
            Bs[buf ^ 1][aCol + 0][aRow] = nb.x;
            Bs[buf ^ 1][aCol + 1][aRow] = nb.y;
            Bs[buf ^ 1][aCol + 2][aRow] = nb.z;
            Bs[buf ^ 1][aCol + 3][aRow] = nb.w;
        }
        __syncthreads();
        buf ^= 1;
    }

#pragma unroll
    for (int a = 0; a < 8; a++) {
        int t = i * 128 + ty * 8 + a;
#pragma unroll
        for (int b = 0; b < 8; b++) {
            int s = j * 128 + tx * 8 + b;
            if (s <= t) {
                float v = acc[a][b];
                attn[(long)t * T_S + s] = (v == 0.0f) ? neg_inf() : v;
            }
        }
    }
}

// ============================================================
// K3: per-row softmax stats (one warp per row)
// ============================================================
__global__ void softmax_stats_kernel(const float* __restrict__ att)
{
    int warp = (blockIdx.x * blockDim.x + threadIdx.x) >> 5;
    int lane = threadIdx.x & 31;
    if (warp >= NT) return;
    int n = warp / T_S, t = warp % T_S;
    const float* row = att + (long)n * T_S * T_S + (long)t * T_S;
    int len = t + 1;

    float m = neg_inf();
    for (int c = lane; c < len; c += 32) m = fmaxf(m, row[c]);
#pragma unroll
    for (int o = 16; o; o >>= 1) m = fmaxf(m, __shfl_xor_sync(0xffffffffu, m, o));

    float s = 0.f;
    for (int c = lane; c < len; c += 32) s += __expf(row[c] - m);
#pragma unroll
    for (int o = 16; o; o >>= 1) s += __shfl_xor_sync(0xffffffffu, s, o);

    if (lane == 0) {
        g_rowmax[warp] = m;
        g_rowsum[warp] = s;
    }
}

// ============================================================
// K4: split-K PV. Block = (row-tile i, K-group jg of <=1024 cols).
// Normalizes+writes att in place, zero-fills above band (last group),
// accumulates out directly (single group) or to g_part.
// ============================================================
__global__ __launch_bounds__(256, 2) void pv_kernel(float* __restrict__ att,
                                                    float* __restrict__ out)
{
    int b = blockIdx.x;  // 0..79, longest-K blocks first (i descending)
    int n = blockIdx.y;
    int i = 31, jg = 0;
    for (i = 31; i >= 0; --i) {
        int g = (i + 8) >> 3;
        if (b < g) { jg = b; break; }
        b -= g;
    }
    int ngroups = (i + 8) >> 3;
    int kStart = jg << 10;
    int kEndA = min((jg + 1) << 10, (i + 1) << 7);
    int kLen = kEndA - kStart;

    float* attn = att + (long)n * T_S * T_S;
    const float* V = g_v + (long)n * T_S * D_E;

    __shared__ float As[2][8][128];
    __shared__ float Bs[2][8][128];
    __shared__ float s_max[128], s_inv[128];

    int tid = threadIdx.x;
    if (tid < 128) {
        int r = n * T_S + (i << 7) + tid;
        s_max[tid] = g_rowmax[r];
        s_inv[tid] = 1.f / g_rowsum[r];
    }
    __syncthreads();

    int tx = tid & 15, ty = tid >> 4;
    int aRow = tid >> 1, aCol = (tid & 1) * 4;
    int bRow = tid >> 5, bCol = (tid & 31) * 4;
    int tGlob = (i << 7) + aRow;
    float rmax = s_max[aRow];
    float rinv = s_inv[aRow];
    float* arow = attn + (long)tGlob * T_S + kStart;

    // initial A (exp-normalize + writeback) and B tiles
    {
        float4 a = *(const float4*)&arow[aCol];
        int s0 = kStart + aCol;
        float p0 = (s0 + 0 <= tGlob) ? __expf(a.x - rmax) * rinv : 0.f;
        float p1 = (s0 + 1 <= tGlob) ? __expf(a.y - rmax) * rinv : 0.f;
        float p2 = (s0 + 2 <= tGlob) ? __expf(a.z - rmax) * rinv : 0.f;
        float p3 = (s0 + 3 <= tGlob) ? __expf(a.w - rmax) * rinv : 0.f;
        As[0][aCol + 0][aRow] = p0;
        As[0][aCol + 1][aRow] = p1;
        As[0][aCol + 2][aRow] = p2;
        As[0][aCol + 3][aRow] = p3;
        *(float4*)&arow[aCol] = make_float4(p0, p1, p2, p3);
        *(float4*)&Bs[0][bRow][bCol] = *(const float4*)&V[(long)(kStart + bRow) * D_E + bCol];
    }
    __syncthreads();

    float acc[8][8];
#pragma unroll
    for (int a = 0; a < 8; a++)
#pragma unroll
        for (int b2 = 0; b2 < 8; b2++) acc[a][b2] = 0.f;

    int buf = 0;
    for (int k0 = 0; k0 < kLen; k0 += 8) {
        float4 na, nb;
        bool more = (k0 + 8 < kLen);
        if (more) {
            na = *(const float4*)&arow[k0 + 8 + aCol];
            nb = *(const float4*)&V[(long)(kStart + k0 + 8 + bRow) * D_E + bCol];
        }
#pragma unroll
        for (int k = 0; k < 8; k++) {
            float ar[8], br[8];
#pragma unroll
            for (int a2 = 0; a2 < 8; a2++) ar[a2] = As[buf][k][ty * 8 + a2];
#pragma unroll
            for (int b2 = 0; b2 < 8; b2++) br[b2] = Bs[buf][k][tx * 8 + b2];
#pragma unroll
            for (int a2 = 0; a2 < 8; a2++)
#pragma unroll
                for (int b2 = 0; b2 < 8; b2++) acc[a2][b2] = fmaf(ar[a2], br[b2], acc[a2][b2]);
        }
        if (more) {
            int s0 = kStart + k0 + 8 + aCol;
            float p0 = (s0 + 0 <= tGlob) ? __expf(na.x - rmax) * rinv : 0.f;
            float p1 = (s0 + 1 <= tGlob) ? __expf(na.y - rmax) * rinv : 0.f;
            float p2 = (s0 + 2 <= tGlob) ? __expf(na.z - rmax) * rinv : 0.f;
            float p3 = (s0 + 3 <= tGlob) ? __expf(na.w - rmax) * rinv : 0.f;
            As[buf ^ 1][aCol + 0][aRow] = p0;
            As[buf ^ 1][aCol + 1][aRow] = p1;
            As[buf ^ 1][aCol + 2][aRow] = p2;
            As[buf ^ 1][aCol + 3][aRow] = p3;
            *(float4*)&arow[k0 + 8 + aCol] = make_float4(p0, p1, p2, p3);
            *(float4*)&Bs[buf ^ 1][bRow][bCol] = nb;
        }
        __syncthreads();
        buf ^= 1;
    }

    // store result tile
    float* dst;
    long rstride;
    if (ngroups == 1) {
        dst = out + ((long)n * T_S + (i << 7)) * D_E;
        rstride = D_E;
    } else {
        dst = g_part + (((long)(n * 24 + (i - 8)) * 4 + jg) << 14);
        rstride = 128;
    }
#pragma unroll
    for (int a = 0; a < 8; a++) {
        long r = (long)(ty * 8 + a) * rstride;
#pragma unroll
        for (int b2 = 0; b2 < 8; b2 += 4) {
            float4 v4 = make_float4(acc[a][b2], acc[a][b2 + 1], acc[a][b2 + 2], acc[a][b2 + 3]);
            *(float4*)&dst[r + tx * 8 + b2] = v4;
        }
    }

    // zero-fill att above the band (last group only)
    if (jg == ngroups - 1) {
        int zstart = (i + 1) << 7;
        int Wd = T_S - zstart;
        if (Wd > 0) {
            long Z = (long)128 * Wd;
            float4 z = make_float4(0.f, 0.f, 0.f, 0.f);
            for (long e = (long)tid * 4; e < Z; e += 1024) {
                int row = (int)(e / Wd);
                int col = (int)(e % Wd);
                *(float4*)&attn[(long)((i << 7) + row) * T_S + zstart + col] = z;
            }
        }
    }
}

// ============================================================
// K5: reduce split-K partials for i >= 8
// ============================================================
__global__ void reduce_kernel(float* __restrict__ out)
{
    int ii = blockIdx.x;  // 0..23  -> i = ii + 8
    int n = blockIdx.y;
    int i = ii + 8;
    int ng = (i + 8) >> 3;
    const float* base = g_part + (((long)(n * 24 + ii) * 4) << 14);
    float* o = out + ((long)n * T_S + (i << 7)) * D_E;
    for (int e = threadIdx.x * 4; e < 128 * 128; e += 1024) {
        float4 s = *(const float4*)&base[e];
        for (int g = 1; g < ng; g++) {
            float4 p = *(const float4*)&base[((long)g << 14) + e];
            s.x += p.x; s.y += p.y; s.z += p.z; s.w += p.w;
        }
        *(float4*)&o[e] = s;
    }
}

// ============================================================
extern "C" void kernel_launch(void* const* d_in, const int* in_sizes, int n_in,
                              void* d_out, int out_size)
{
    const float* x  = (const float*)d_in[0];
    const float* Wq = (const float*)d_in[1];
    const float* Wk = (const float*)d_in[2];
    const float* Wv = (const float*)d_in[3];

    const long NTD = (long)NT * D_E;
    const long NTT = (long)N_B * T_S * T_S;

    float* dout = (float*)d_out;
    float* out_ptr;
    float* att_ptr;
    if ((long)out_size >= NTD + NTT) {
        out_ptr = dout;
        att_ptr = dout + NTD;
    } else if ((long)out_size == NTT) {
        att_ptr = dout;
        void* fb = nullptr;
        cudaGetSymbolAddress(&fb, g_out_fallback);
        out_ptr = (float*)fb;
    } else {
        out_ptr = dout;
        att_ptr = dout;
    }

    qkv_gemm_kernel<<<dim3(NT / 128, 3), 256>>>(x, Wq, Wk, Wv);

    int nTiles = T_S / 128;
    int nTri = nTiles * (nTiles + 1) / 2;
    scores_kernel<<<dim3(nTri, N_B), 256>>>(att_ptr);

    softmax_stats_kernel<<<NT / 8, 256>>>(att_ptr);

    pv_kernel<<<dim3(80, N_B), 256>>>(att_ptr, out_ptr);

    reduce_kernel<<<dim3(24, N_B), 256>>>(out_ptr);
}

// round 4
// speedup vs baseline: 2.9346x; 1.7231x over previous
#include <cuda_runtime.h>
#include <cuda_bf16.h>
#include <math.h>
#include <stdint.h>

#define N_B 4
#define T_S 4096
#define DIN 1024
#define D_E 128
#define NT (N_B * T_S)
#define PCH 40  // smem row pitch in halfs (32 + 8 pad)

// ---- scratch (device globals: allocation-free) ----
__device__ __nv_bfloat16 g_xh[(long)NT * DIN];
__device__ __nv_bfloat16 g_xl[(long)NT * DIN];
__device__ __nv_bfloat16 g_wth[3 * D_E * DIN];
__device__ __nv_bfloat16 g_wtl[3 * D_E * DIN];
__device__ __nv_bfloat16 g_qh[NT * D_E];
__device__ __nv_bfloat16 g_ql[NT * D_E];
__device__ __nv_bfloat16 g_kh[NT * D_E];
__device__ __nv_bfloat16 g_kl[NT * D_E];
__device__ __nv_bfloat16 g_vth[(long)N_B * D_E * T_S];
__device__ __nv_bfloat16 g_vtl[(long)N_B * D_E * T_S];
__device__ float g_rowmax[NT];
__device__ float g_rowsum[NT];
__device__ float g_part[(long)4 * 24 * 4 * 128 * 128];
__device__ float g_out_fallback[NT * D_E];

__device__ __forceinline__ float neg_inf() { return __int_as_float(0xff800000); }

__device__ __forceinline__ uint32_t smem_u32(const void* p) {
    uint32_t a;
    asm("{ .reg .u64 t; cvta.to.shared.u64 t, %1; cvt.u32.u64 %0, t; }" : "=r"(a) : "l"(p));
    return a;
}
__device__ __forceinline__ void split_bf16(float x, __nv_bfloat16& h, __nv_bfloat16& l) {
    h = __float2bfloat16(x);
    l = __float2bfloat16(x - __bfloat162float(h));
}

#define CP16(dst, src) asm volatile("cp.async.cg.shared.global [%0], [%1], 16;" :: "r"(dst), "l"(src))
#define CPCOMMIT() asm volatile("cp.async.commit_group;" ::: "memory")
#define CPWAIT1() asm volatile("cp.async.wait_group 1;" ::: "memory")
#define CPWAIT0() asm volatile("cp.async.wait_group 0;" ::: "memory")

__device__ __forceinline__ void ldsm_x4(uint32_t* r, uint32_t addr) {
    asm volatile("ldmatrix.sync.aligned.m8n8.x4.shared.b16 {%0,%1,%2,%3}, [%4];"
        : "=r"(r[0]), "=r"(r[1]), "=r"(r[2]), "=r"(r[3]) : "r"(addr));
}
__device__ __forceinline__ void ldsm_x2(uint32_t* r, uint32_t addr) {
    asm volatile("ldmatrix.sync.aligned.m8n8.x2.shared.b16 {%0,%1}, [%2];"
        : "=r"(r[0]), "=r"(r[1]) : "r"(addr));
}
__device__ __forceinline__ void mma_bf16(float* c, const uint32_t* a, const uint32_t* b) {
    asm volatile(
        "mma.sync.aligned.m16n8k16.row.col.f32.bf16.bf16.f32 "
        "{%0,%1,%2,%3}, {%4,%5,%6,%7}, {%8,%9}, {%0,%1,%2,%3};"
        : "+f"(c[0]), "+f"(c[1]), "+f"(c[2]), "+f"(c[3])
        : "r"(a[0]), "r"(a[1]), "r"(a[2]), "r"(a[3]), "r"(b[0]), "r"(b[1]));
}

// One k16 step of the 64x32 warp tile, bf16-split (3 mma per frag pair).
// smem layout per stage buf: Ah@0, Al@10240, Bh@20480, Bl@30720 (bytes), pitch PCH halfs.
__device__ __forceinline__ void mma_tile_step(uint32_t sb, int buf, int ks,
                                              int wm, int wn, int lane,
                                              float (*acc)[4][4])
{
    uint32_t base = sb + buf * 40960;
    uint32_t ah[4][4], al[4][4], bh[4][2], bl[4][2];
    int arow = lane & 15;
    int acol = ks * 16 + (lane >> 4) * 8;
#pragma unroll
    for (int mt = 0; mt < 4; mt++) {
        uint32_t ro = (uint32_t)(wm + mt * 16 + arow) * (PCH * 2) + acol * 2;
        ldsm_x4(ah[mt], base + ro);
        ldsm_x4(al[mt], base + 10240 + ro);
    }
    int l = lane & 15;
    int brow = l & 7;
    int bcol = ks * 16 + ((l >> 3) & 1) * 8;
#pragma unroll
    for (int nt = 0; nt < 4; nt++) {
        uint32_t ro = (uint32_t)(wn + nt * 8 + brow) * (PCH * 2) + bcol * 2;
        ldsm_x2(bh[nt], base + 20480 + ro);
        ldsm_x2(bl[nt], base + 30720 + ro);
    }
#pragma unroll
    for (int mt = 0; mt < 4; mt++)
#pragma unroll
        for (int nt = 0; nt < 4; nt++) {
            mma_bf16(acc[mt][nt], ah[mt], bh[nt]);
            mma_bf16(acc[mt][nt], ah[mt], bl[nt]);
            mma_bf16(acc[mt][nt], al[mt], bh[nt]);
        }
}

// ============================================================
// K-1: split x into bf16 hi/lo
// ============================================================
__global__ __launch_bounds__(256) void splitx_kernel(const float* __restrict__ x)
{
    long idx = ((long)blockIdx.x * 256 + threadIdx.x) * 4;
    float4 a = *(const float4*)&x[idx];
    __nv_bfloat16 h0, h1, h2, h3, l0, l1, l2, l3;
    split_bf16(a.x, h0, l0);
    split_bf16(a.y, h1, l1);
    split_bf16(a.z, h2, l2);
    split_bf16(a.w, h3, l3);
    __nv_bfloat162 ph0, ph1, pl0, pl1;
    ph0.x = h0; ph0.y = h1; ph1.x = h2; ph1.y = h3;
    pl0.x = l0; pl0.y = l1; pl1.x = l2; pl1.y = l3;
    *(uint2*)&g_xh[idx] = make_uint2(*(uint32_t*)&ph0, *(uint32_t*)&ph1);
    *(uint2*)&g_xl[idx] = make_uint2(*(uint32_t*)&pl0, *(uint32_t*)&pl1);
}

// ============================================================
// K0: transpose + split W
// ============================================================
__global__ __launch_bounds__(256) void wt_kernel(const float* __restrict__ Wq,
                                                 const float* __restrict__ Wk,
                                                 const float* __restrict__ Wv)
{
    const float* W = (blockIdx.z == 0) ? Wq : ((blockIdx.z == 1) ? Wk : Wv);
    __shared__ float t[32][33];
    int tid = threadIdx.x;
    int tx = tid & 31, ty = tid >> 5;
    int k0 = blockIdx.x * 32, n0 = blockIdx.y * 32;
#pragma unroll
    for (int s = 0; s < 4; s++) t[ty + s * 8][tx] = W[(k0 + ty + s * 8) * D_E + n0 + tx];
    __syncthreads();
    long wb = (long)blockIdx.z * D_E * DIN;
#pragma unroll
    for (int s = 0; s < 4; s++) {
        int n = n0 + ty + s * 8, k = k0 + tx;
        __nv_bfloat16 h, l;
        split_bf16(t[tx][ty + s * 8], h, l);
        g_wth[wb + (long)n * DIN + k] = h;
        g_wtl[wb + (long)n * DIN + k] = l;
    }
}

// ============================================================
// K1: QKV via mma.sync bf16-split. grid (NT/128, 3)
// ============================================================
__global__ __launch_bounds__(256, 1) void qkv_mma_kernel()
{
    extern __shared__ char smc[];
    uint32_t sb = smem_u32(smc);
    int tid = threadIdx.x, lane = tid & 31, wid = tid >> 5;
    int w = blockIdx.y;
    long mBase = (long)blockIdx.x * 128;

    const __nv_bfloat16* sAh = g_xh + mBase * DIN;
    const __nv_bfloat16* sAl = g_xl + mBase * DIN;
    const __nv_bfloat16* sBh = g_wth + (long)w * D_E * DIN;
    const __nv_bfloat16* sBl = g_wtl + (long)w * D_E * DIN;

    int wm = (wid >> 2) * 64, wn = (wid & 3) * 32;
    float acc[4][4][4];
#pragma unroll
    for (int a = 0; a < 4; a++)
#pragma unroll
        for (int b = 0; b < 4; b++)
#pragma unroll
            for (int cc = 0; cc < 4; cc++) acc[a][b][cc] = 0.f;

#define QKV_LOAD(c)                                                            \
    {                                                                          \
        int buf_ = (c) & 1;                                                    \
        int k0_ = (c) * 32;                                                    \
        uint32_t db_ = sb + buf_ * 40960;                                      \
        for (int u = tid; u < 2048; u += 256) {                                \
            int arr = u >> 9, idx = u & 511, row = idx >> 2, seg = idx & 3;    \
            const __nv_bfloat16* s =                                           \
                (arr == 0) ? sAh : (arr == 1) ? sAl : (arr == 2) ? sBh : sBl;  \
            CP16(db_ + arr * 10240 + row * 80 + seg * 16,                      \
                 s + (long)row * DIN + k0_ + seg * 8);                         \
        }                                                                      \
        CPCOMMIT();                                                            \
    }

    QKV_LOAD(0);
    for (int c = 0; c < 32; c++) {
        if (c + 1 < 32) { QKV_LOAD(c + 1); CPWAIT1(); } else { CPWAIT0(); }
        __syncthreads();
        mma_tile_step(sb, c & 1, 0, wm, wn, lane, acc);
        mma_tile_step(sb, c & 1, 1, wm, wn, lane, acc);
        __syncthreads();
    }
#undef QKV_LOAD

    if (w < 2) {
        __nv_bfloat16* dh = w ? g_kh : g_qh;
        __nv_bfloat16* dl = w ? g_kl : g_ql;
#pragma unroll
        for (int mt = 0; mt < 4; mt++)
#pragma unroll
            for (int nt = 0; nt < 4; nt++) {
                int cc = wn + nt * 8 + (lane & 3) * 2;
#pragma unroll
                for (int h = 0; h < 2; h++) {
                    int row = wm + mt * 16 + (lane >> 2) + h * 8;
                    float v0 = acc[mt][nt][h * 2], v1 = acc[mt][nt][h * 2 + 1];
                    __nv_bfloat16 h0, h1, l0, l1;
                    split_bf16(v0, h0, l0);
                    split_bf16(v1, h1, l1);
                    __nv_bfloat162 ph, pl;
                    ph.x = h0; ph.y = h1; pl.x = l0; pl.y = l1;
                    long o = (mBase + row) * D_E + cc;
                    *(__nv_bfloat162*)&dh[o] = ph;
                    *(__nv_bfloat162*)&dl[o] = pl;
                }
            }
    } else {
        // V: stage + transpose -> g_vth/g_vtl [n][d][t]
        float* stage = (float*)smc;  // 128 x 129 f32
#pragma unroll
        for (int mt = 0; mt < 4; mt++)
#pragma unroll
            for (int nt = 0; nt < 4; nt++) {
                int cc = wn + nt * 8 + (lane & 3) * 2;
#pragma unroll
                for (int h = 0; h < 2; h++) {
                    int row = wm + mt * 16 + (lane >> 2) + h * 8;
                    stage[row * 129 + cc] = acc[mt][nt][h * 2];
                    stage[row * 129 + cc + 1] = acc[mt][nt][h * 2 + 1];
                }
            }
        __syncthreads();
        int nb = (int)(mBase >> 12);
        int tb = (int)(mBase & (T_S - 1));
        for (int u = tid; u < 8192; u += 256) {
            int d = u >> 6, tp = (u & 63) * 2;
            float v0 = stage[tp * 129 + d];
            float v1 = stage[(tp + 1) * 129 + d];
            __nv_bfloat16 h0, h1, l0, l1;
            split_bf16(v0, h0, l0);
            split_bf16(v1, h1, l1);
            __nv_bfloat162 ph, pl;
            ph.x = h0; ph.y = h1; pl.x = l0; pl.y = l1;
            long o = ((long)nb * D_E + d) * T_S + tb + tp;
            *(__nv_bfloat162*)&g_vth[o] = ph;
            *(__nv_bfloat162*)&g_vtl[o] = pl;
        }
    }
}

// ============================================================
// K2: scores S = Q K^T on lower-tri tiles via mma.sync
// ============================================================
__global__ __launch_bounds__(256, 1) void scores_mma_kernel(float* __restrict__ att)
{
    int tri = blockIdx.x;
    int n = blockIdx.y;
    int i = (int)((sqrtf(8.f * tri + 1.f) - 1.f) * 0.5f);
    while ((i + 1) * (i + 2) / 2 <= tri) i++;
    while (i * (i + 1) / 2 > tri) i--;
    int j = tri - i * (i + 1) / 2;

    extern __shared__ char smc[];
    uint32_t sb = smem_u32(smc);
    int tid = threadIdx.x, lane = tid & 31, wid = tid >> 5;

    const __nv_bfloat16* sAh = g_qh + ((long)n * T_S + i * 128) * D_E;
    const __nv_bfloat16* sAl = g_ql + ((long)n * T_S + i * 128) * D_E;
    const __nv_bfloat16* sBh = g_kh + ((long)n * T_S + j * 128) * D_E;
    const __nv_bfloat16* sBl = g_kl + ((long)n * T_S + j * 128) * D_E;

    int wm = (wid >> 2) * 64, wn = (wid & 3) * 32;
    float acc[4][4][4];
#pragma unroll
    for (int a = 0; a < 4; a++)
#pragma unroll
        for (int b = 0; b < 4; b++)
#pragma unroll
            for (int cc = 0; cc < 4; cc++) acc[a][b][cc] = 0.f;

#define SC_LOAD(c)                                                             \
    {                                                                          \
        int buf_ = (c) & 1;                                                    \
        int k0_ = (c) * 32;                                                    \
        uint32_t db_ = sb + buf_ * 40960;                                      \
        for (int u = tid; u < 2048; u += 256) {                                \
            int arr = u >> 9, idx = u & 511, row = idx >> 2, seg = idx & 3;    \
            const __nv_bfloat16* s =                                           \
                (arr == 0) ? sAh : (arr == 1) ? sAl : (arr == 2) ? sBh : sBl;  \
            CP16(db_ + arr * 10240 + row * 80 + seg * 16,                      \
                 s + (long)row * D_E + k0_ + seg * 8);                         \
        }                                                                      \
        CPCOMMIT();                                                            \
    }

    SC_LOAD(0);
    for (int c = 0; c < 4; c++) {
        if (c + 1 < 4) { SC_LOAD(c + 1); CPWAIT1(); } else { CPWAIT0(); }
        __syncthreads();
        mma_tile_step(sb, c & 1, 0, wm, wn, lane, acc);
        mma_tile_step(sb, c & 1, 1, wm, wn, lane, acc);
        __syncthreads();
    }
#undef SC_LOAD

    float* attn = att + (long)n * T_S * T_S;
#pragma unroll
    for (int mt = 0; mt < 4; mt++)
#pragma unroll
        for (int nt = 0; nt < 4; nt++) {
            int s0 = j * 128 + wn + nt * 8 + (lane & 3) * 2;
#pragma unroll
            for (int h = 0; h < 2; h++) {
                int t = i * 128 + wm + mt * 16 + (lane >> 2) + h * 8;
                float v0 = acc[mt][nt][h * 2], v1 = acc[mt][nt][h * 2 + 1];
                if (s0 <= t) attn[(long)t * T_S + s0] = (v0 == 0.0f) ? neg_inf() : v0;
                if (s0 + 1 <= t) attn[(long)t * T_S + s0 + 1] = (v1 == 0.0f) ? neg_inf() : v1;
            }
        }
}

// ============================================================
// K3: per-row softmax stats
// ============================================================
__global__ void softmax_stats_kernel(const float* __restrict__ att)
{
    int warp = (blockIdx.x * blockDim.x + threadIdx.x) >> 5;
    int lane = threadIdx.x & 31;
    if (warp >= NT) return;
    int n = warp / T_S, t = warp % T_S;
    const float* row = att + (long)n * T_S * T_S + (long)t * T_S;
    int len = t + 1;

    float m = neg_inf();
    for (int c = lane; c < len; c += 32) m = fmaxf(m, row[c]);
#pragma unroll
    for (int o = 16; o; o >>= 1) m = fmaxf(m, __shfl_xor_sync(0xffffffffu, m, o));

    float s = 0.f;
    for (int c = lane; c < len; c += 32) s += __expf(row[c] - m);
#pragma unroll
    for (int o = 16; o; o >>= 1) s += __shfl_xor_sync(0xffffffffu, s, o);

    if (lane == 0) {
        g_rowmax[warp] = m;
        g_rowsum[warp] = s;
    }
}

// ============================================================
// K4: split-K PV via mma.sync. A = P (exp on the fly, written back),
// B = vt bf16 hi/lo. grid (80, N_B).
// ============================================================
__global__ __launch_bounds__(256, 1) void pv_mma_kernel(float* __restrict__ att,
                                                        float* __restrict__ out)
{
    int b = blockIdx.x;
    int n = blockIdx.y;
    int i = 31, jg = 0;
    for (i = 31; i >= 0; --i) {
        int g = (i + 8) >> 3;
        if (b < g) { jg = b; break; }
        b -= g;
    }
    int ngroups = (i + 8) >> 3;
    int kStart = jg << 10;
    int kEndA = min((jg + 1) << 10, (i + 1) << 7);
    int nc = (kEndA - kStart) >> 5;

    extern __shared__ char smc[];
    uint32_t sb = smem_u32(smc);
    float* smax = (float*)(smc + 81920);
    float* sinv = (float*)(smc + 82432);
    int tid = threadIdx.x, lane = tid & 31, wid = tid >> 5;

    float* attn = att + (long)n * T_S * T_S;

    if (tid < 128) {
        int r = n * T_S + (i << 7) + tid;
        smax[tid] = g_rowmax[r];
        sinv[tid] = 1.f / g_rowsum[r];
    }
    __syncthreads();

    int wm = (wid >> 2) * 64, wn = (wid & 3) * 32;
    float acc[4][4][4];
#pragma unroll
    for (int a = 0; a < 4; a++)
#pragma unroll
        for (int b2 = 0; b2 < 4; b2++)
#pragma unroll
            for (int cc = 0; cc < 4; cc++) acc[a][b2][cc] = 0.f;

#define PV_LDB(c)                                                              \
    {                                                                          \
        int buf_ = (c) & 1;                                                    \
        int k0_ = kStart + (c) * 32;                                           \
        uint32_t db_ = sb + buf_ * 40960 + 20480;                              \
        for (int u = tid; u < 1024; u += 256) {                                \
            int arr = u >> 9, idx = u & 511, row = idx >> 2, seg = idx & 3;    \
            const __nv_bfloat16* s = (arr ? g_vtl : g_vth) +                   \
                ((long)n * D_E + row) * T_S + k0_ + seg * 8;                   \
            CP16(db_ + arr * 10240 + row * 80 + seg * 16, s);                  \
        }                                                                      \
        CPCOMMIT();                                                            \
    }

#define PV_LDA(c, ar)                                                          \
    {                                                                          \
        int k0_ = kStart + (c) * 32;                                           \
        _Pragma("unroll") for (int q = 0; q < 4; q++) {                        \
            int idx = tid + q * 256;                                           \
            int row = idx >> 3, seg = idx & 7;                                 \
            ar[q] = *(const float4*)&attn[(long)((i << 7) + row) * T_S + k0_ + seg * 4]; \
        }                                                                      \
    }

#define PV_PROC(c, ar)                                                         \
    {                                                                          \
        int k0_ = kStart + (c) * 32;                                           \
        uint32_t db_ = sb + ((c) & 1) * 40960;                                 \
        _Pragma("unroll") for (int q = 0; q < 4; q++) {                        \
            int idx = tid + q * 256;                                           \
            int row = idx >> 3, seg = idx & 7;                                 \
            int t = (i << 7) + row;                                            \
            int s0 = k0_ + seg * 4;                                            \
            float rm = smax[row], ri = sinv[row];                              \
            float p0 = (s0 + 0 <= t) ? __expf(ar[q].x - rm) * ri : 0.f;        \
            float p1 = (s0 + 1 <= t) ? __expf(ar[q].y - rm) * ri : 0.f;        \
            float p2 = (s0 + 2 <= t) ? __expf(ar[q].z - rm) * ri : 0.f;        \
            float p3 = (s0 + 3 <= t) ? __expf(ar[q].w - rm) * ri : 0.f;        \
            *(float4*)&attn[(long)t * T_S + s0] = make_float4(p0, p1, p2, p3); \
            __nv_bfloat16 h0, h1, h2, h3, l0, l1, l2, l3;                      \
            split_bf16(p0, h0, l0); split_bf16(p1, h1, l1);                    \
            split_bf16(p2, h2, l2); split_bf16(p3, h3, l3);                    \
            __nv_bfloat162 ph0, ph1, pl0, pl1;                                 \
            ph0.x = h0; ph0.y = h1; ph1.x = h2; ph1.y = h3;                    \
            pl0.x = l0; pl0.y = l1; pl1.x = l2; pl1.y = l3;                    \
            uint32_t so = row * 80 + seg * 8;                                  \
            *(uint2*)(smc + (((c) & 1) * 40960) + so) =                        \
                make_uint2(*(uint32_t*)&ph0, *(uint32_t*)&ph1);                \
            *(uint2*)(smc + (((c) & 1) * 40960) + 10240 + so) =                \
                make_uint2(*(uint32_t*)&pl0, *(uint32_t*)&pl1);                \
            (void)db_;                                                         \
        }                                                                      \
    }

    float4 arA[4], arN[4];
    PV_LDB(0);
    PV_LDA(0, arA);
    PV_PROC(0, arA);

    for (int c = 0; c < nc; c++) {
        if (c + 1 < nc) {
            PV_LDB(c + 1);
            PV_LDA(c + 1, arN);
            CPWAIT1();
        } else {
            CPWAIT0();
        }
        __syncthreads();
        mma_tile_step(sb, c & 1, 0, wm, wn, lane, acc);
        mma_tile_step(sb, c & 1, 1, wm, wn, lane, acc);
        if (c + 1 < nc) PV_PROC(c + 1, arN);
        __syncthreads();
    }
#undef PV_LDB
#undef PV_LDA
#undef PV_PROC

    float* dst;
    if (ngroups == 1) dst = out + ((long)n * T_S + (i << 7)) * D_E;
    else dst = g_part + (((long)(n * 24 + (i - 8)) * 4 + jg) << 14);
#pragma unroll
    for (int mt = 0; mt < 4; mt++)
#pragma unroll
        for (int nt = 0; nt < 4; nt++) {
            int cc = wn + nt * 8 + (lane & 3) * 2;
#pragma unroll
            for (int h = 0; h < 2; h++) {
                int row = wm + mt * 16 + (lane >> 2) + h * 8;
                *(float2*)&dst[(long)row * 128 + cc] =
                    make_float2(acc[mt][nt][h * 2], acc[mt][nt][h * 2 + 1]);
            }
        }

    if (jg == ngroups - 1) {
        int zstart = (i + 1) << 7;
        int Wd = T_S - zstart;
        if (Wd > 0) {
            long Z = (long)128 * Wd;
            float4 z = make_float4(0.f, 0.f, 0.f, 0.f);
            for (long e = (long)tid * 4; e < Z; e += 1024) {
                int row = (int)(e / Wd);
                int col = (int)(e % Wd);
                *(float4*)&attn[(long)((i << 7) + row) * T_S + zstart + col] = z;
            }
        }
    }
}

// ============================================================
// K5: reduce split-K partials
// ============================================================
__global__ void reduce_kernel(float* __restrict__ out)
{
    int ii = blockIdx.x;
    int n = blockIdx.y;
    int i = ii + 8;
    int ng = (i + 8) >> 3;
    const float* base = g_part + (((long)(n * 24 + ii) * 4) << 14);
    float* o = out + ((long)n * T_S + (i << 7)) * D_E;
    for (int e = threadIdx.x * 4; e < 128 * 128; e += 1024) {
        float4 s = *(const float4*)&base[e];
        for (int g = 1; g < ng; g++) {
            float4 p = *(const float4*)&base[((long)g << 14) + e];
            s.x += p.x; s.y += p.y; s.z += p.z; s.w += p.w;
        }
        *(float4*)&o[e] = s;
    }
}

// ============================================================
extern "C" void kernel_launch(void* const* d_in, const int* in_sizes, int n_in,
                              void* d_out, int out_size)
{
    const float* x  = (const float*)d_in[0];
    const float* Wq = (const float*)d_in[1];
    const float* Wk = (const float*)d_in[2];
    const float* Wv = (const float*)d_in[3];

    const long NTD = (long)NT * D_E;
    const long NTT = (long)N_B * T_S * T_S;

    float* dout = (float*)d_out;
    float* out_ptr;
    float* att_ptr;
    if ((long)out_size >= NTD + NTT) {
        out_ptr = dout;
        att_ptr = dout + NTD;
    } else if ((long)out_size == NTT) {
        att_ptr = dout;
        void* fb = nullptr;
        cudaGetSymbolAddress(&fb, g_out_fallback);
        out_ptr = (float*)fb;
    } else {
        out_ptr = dout;
        att_ptr = dout;
    }

    cudaFuncSetAttribute(qkv_mma_kernel, cudaFuncAttributeMaxDynamicSharedMemorySize, 81920);
    cudaFuncSetAttribute(scores_mma_kernel, cudaFuncAttributeMaxDynamicSharedMemorySize, 81920);
    cudaFuncSetAttribute(pv_mma_kernel, cudaFuncAttributeMaxDynamicSharedMemorySize, 82944);

    splitx_kernel<<<(long)NT * DIN / 1024, 256>>>(x);
    wt_kernel<<<dim3(DIN / 32, D_E / 32, 3), 256>>>(Wq, Wk, Wv);

    qkv_mma_kernel<<<dim3(NT / 128, 3), 256, 81920>>>();

    int nTiles = T_S / 128;
    int nTri = nTiles * (nTiles + 1) / 2;
    scores_mma_kernel<<<dim3(nTri, N_B), 256, 81920>>>(att_ptr);

    softmax_stats_kernel<<<NT / 8, 256>>>(att_ptr);

    pv_mma_kernel<<<dim3(80, N_B), 256, 82944>>>(att_ptr, out_ptr);

    reduce_kernel<<<dim3(24, N_B), 256>>>(out_ptr);
}

// round 5
// speedup vs baseline: 3.0068x; 1.0246x over previous
#include <cuda_runtime.h>
#include <cuda_bf16.h>
#include <math.h>
#include <stdint.h>

#define N_B 4
#define T_S 4096
#define DIN 1024
#define D_E 128
#define NT (N_B * T_S)
#define PCH 40  // smem row pitch in halfs (32 + 8 pad) for BK=32 kernels

// ---- scratch (device globals: allocation-free) ----
__device__ __nv_bfloat16 g_xh[(long)NT * DIN];
__device__ __nv_bfloat16 g_xl[(long)NT * DIN];
__device__ __nv_bfloat16 g_wth[3 * D_E * DIN];
__device__ __nv_bfloat16 g_wtl[3 * D_E * DIN];
__device__ __nv_bfloat16 g_qh[NT * D_E];
__device__ __nv_bfloat16 g_ql[NT * D_E];
__device__ __nv_bfloat16 g_kh[NT * D_E];
__device__ __nv_bfloat16 g_kl[NT * D_E];
__device__ __nv_bfloat16 g_vth[(long)N_B * D_E * T_S];
__device__ __nv_bfloat16 g_vtl[(long)N_B * D_E * T_S];
__device__ float g_pmax[(long)NT * 32];
__device__ float g_psum[(long)NT * 32];
__device__ float g_rowmax[NT];
__device__ float g_rowsum[NT];
__device__ float g_part[(long)4 * 24 * 4 * 128 * 128];
__device__ float g_out_fallback[NT * D_E];

__device__ __forceinline__ float neg_inf() { return __int_as_float(0xff800000); }

__device__ __forceinline__ uint32_t smem_u32(const void* p) {
    uint32_t a;
    asm("{ .reg .u64 t; cvta.to.shared.u64 t, %1; cvt.u32.u64 %0, t; }" : "=r"(a) : "l"(p));
    return a;
}
__device__ __forceinline__ void split_bf16(float x, __nv_bfloat16& h, __nv_bfloat16& l) {
    h = __float2bfloat16(x);
    l = __float2bfloat16(x - __bfloat162float(h));
}

#define CP16(dst, src) asm volatile("cp.async.cg.shared.global [%0], [%1], 16;" :: "r"(dst), "l"(src))
#define CPCOMMIT() asm volatile("cp.async.commit_group;" ::: "memory")
#define CPWAIT1() asm volatile("cp.async.wait_group 1;" ::: "memory")
#define CPWAIT0() asm volatile("cp.async.wait_group 0;" ::: "memory")

__device__ __forceinline__ void ldsm_x4(uint32_t* r, uint32_t addr) {
    asm volatile("ldmatrix.sync.aligned.m8n8.x4.shared.b16 {%0,%1,%2,%3}, [%4];"
        : "=r"(r[0]), "=r"(r[1]), "=r"(r[2]), "=r"(r[3]) : "r"(addr));
}
__device__ __forceinline__ void ldsm_x2(uint32_t* r, uint32_t addr) {
    asm volatile("ldmatrix.sync.aligned.m8n8.x2.shared.b16 {%0,%1}, [%2];"
        : "=r"(r[0]), "=r"(r[1]) : "r"(addr));
}
__device__ __forceinline__ void mma_bf16(float* c, const uint32_t* a, const uint32_t* b) {
    asm volatile(
        "mma.sync.aligned.m16n8k16.row.col.f32.bf16.bf16.f32 "
        "{%0,%1,%2,%3}, {%4,%5,%6,%7}, {%8,%9}, {%0,%1,%2,%3};"
        : "+f"(c[0]), "+f"(c[1]), "+f"(c[2]), "+f"(c[3])
        : "r"(a[0]), "r"(a[1]), "r"(a[2]), "r"(a[3]), "r"(b[0]), "r"(b[1]));
}

// One k16 step of the 64x32 warp tile, bf16-split (3 mma per frag pair).
// smem layout per stage buf: Ah@0, Al@10240, Bh@20480, Bl@30720 (bytes), pitch PCH halfs.
__device__ __forceinline__ void mma_tile_step(uint32_t sb, int buf, int ks,
                                              int wm, int wn, int lane,
                                              float (*acc)[4][4])
{
    uint32_t base = sb + buf * 40960;
    uint32_t ah[4][4], al[4][4], bh[4][2], bl[4][2];
    int arow = lane & 15;
    int acol = ks * 16 + (lane >> 4) * 8;
#pragma unroll
    for (int mt = 0; mt < 4; mt++) {
        uint32_t ro = (uint32_t)(wm + mt * 16 + arow) * (PCH * 2) + acol * 2;
        ldsm_x4(ah[mt], base + ro);
        ldsm_x4(al[mt], base + 10240 + ro);
    }
    int l = lane & 15;
    int brow = l & 7;
    int bcol = ks * 16 + ((l >> 3) & 1) * 8;
#pragma unroll
    for (int nt = 0; nt < 4; nt++) {
        uint32_t ro = (uint32_t)(wn + nt * 8 + brow) * (PCH * 2) + bcol * 2;
        ldsm_x2(bh[nt], base + 20480 + ro);
        ldsm_x2(bl[nt], base + 30720 + ro);
    }
#pragma unroll
    for (int mt = 0; mt < 4; mt++)
#pragma unroll
        for (int nt = 0; nt < 4; nt++) {
            mma_bf16(acc[mt][nt], ah[mt], bh[nt]);
            mma_bf16(acc[mt][nt], ah[mt], bl[nt]);
            mma_bf16(acc[mt][nt], al[mt], bh[nt]);
        }
}

// ============================================================
// K-1: split x into bf16 hi/lo
// ============================================================
__global__ __launch_bounds__(256) void splitx_kernel(const float* __restrict__ x)
{
    long idx = ((long)blockIdx.x * 256 + threadIdx.x) * 4;
    float4 a = *(const float4*)&x[idx];
    __nv_bfloat16 h0, h1, h2, h3, l0, l1, l2, l3;
    split_bf16(a.x, h0, l0);
    split_bf16(a.y, h1, l1);
    split_bf16(a.z, h2, l2);
    split_bf16(a.w, h3, l3);
    __nv_bfloat162 ph0, ph1, pl0, pl1;
    ph0.x = h0; ph0.y = h1; ph1.x = h2; ph1.y = h3;
    pl0.x = l0; pl0.y = l1; pl1.x = l2; pl1.y = l3;
    *(uint2*)&g_xh[idx] = make_uint2(*(uint32_t*)&ph0, *(uint32_t*)&ph1);
    *(uint2*)&g_xl[idx] = make_uint2(*(uint32_t*)&pl0, *(uint32_t*)&pl1);
}

// ============================================================
// K0: transpose + split W
// ============================================================
__global__ __launch_bounds__(256) void wt_kernel(const float* __restrict__ Wq,
                                                 const float* __restrict__ Wk,
                                                 const float* __restrict__ Wv)
{
    const float* W = (blockIdx.z == 0) ? Wq : ((blockIdx.z == 1) ? Wk : Wv);
    __shared__ float t[32][33];
    int tid = threadIdx.x;
    int tx = tid & 31, ty = tid >> 5;
    int k0 = blockIdx.x * 32, n0 = blockIdx.y * 32;
#pragma unroll
    for (int s = 0; s < 4; s++) t[ty + s * 8][tx] = W[(k0 + ty + s * 8) * D_E + n0 + tx];
    __syncthreads();
    long wb = (long)blockIdx.z * D_E * DIN;
#pragma unroll
    for (int s = 0; s < 4; s++) {
        int n = n0 + ty + s * 8, k = k0 + tx;
        __nv_bfloat16 h, l;
        split_bf16(t[tx][ty + s * 8], h, l);
        g_wth[wb + (long)n * DIN + k] = h;
        g_wtl[wb + (long)n * DIN + k] = l;
    }
}

// ============================================================
// K1: QKV via mma.sync bf16-split. grid (NT/128, 3)
// ============================================================
__global__ __launch_bounds__(256, 1) void qkv_mma_kernel()
{
    extern __shared__ char smc[];
    uint32_t sb = smem_u32(smc);
    int tid = threadIdx.x, lane = tid & 31, wid = tid >> 5;
    int w = blockIdx.y;
    long mBase = (long)blockIdx.x * 128;

    const __nv_bfloat16* sAh = g_xh + mBase * DIN;
    const __nv_bfloat16* sAl = g_xl + mBase * DIN;
    const __nv_bfloat16* sBh = g_wth + (long)w * D_E * DIN;
    const __nv_bfloat16* sBl = g_wtl + (long)w * D_E * DIN;

    int wm = (wid >> 2) * 64, wn = (wid & 3) * 32;
    float acc[4][4][4];
#pragma unroll
    for (int a = 0; a < 4; a++)
#pragma unroll
        for (int b = 0; b < 4; b++)
#pragma unroll
            for (int cc = 0; cc < 4; cc++) acc[a][b][cc] = 0.f;

#define QKV_LOAD(c)                                                            \
    {                                                                          \
        int buf_ = (c) & 1;                                                    \
        int k0_ = (c) * 32;                                                    \
        uint32_t db_ = sb + buf_ * 40960;                                      \
        for (int u = tid; u < 2048; u += 256) {                                \
            int arr = u >> 9, idx = u & 511, row = idx >> 2, seg = idx & 3;    \
            const __nv_bfloat16* s =                                           \
                (arr == 0) ? sAh : (arr == 1) ? sAl : (arr == 2) ? sBh : sBl;  \
            CP16(db_ + arr * 10240 + row * 80 + seg * 16,                      \
                 s + (long)row * DIN + k0_ + seg * 8);                         \
        }                                                                      \
        CPCOMMIT();                                                            \
    }

    QKV_LOAD(0);
    for (int c = 0; c < 32; c++) {
        if (c + 1 < 32) { QKV_LOAD(c + 1); CPWAIT1(); } else { CPWAIT0(); }
        __syncthreads();
        mma_tile_step(sb, c & 1, 0, wm, wn, lane, acc);
        mma_tile_step(sb, c & 1, 1, wm, wn, lane, acc);
        __syncthreads();
    }
#undef QKV_LOAD

    if (w < 2) {
        __nv_bfloat16* dh = w ? g_kh : g_qh;
        __nv_bfloat16* dl = w ? g_kl : g_ql;
#pragma unroll
        for (int mt = 0; mt < 4; mt++)
#pragma unroll
            for (int nt = 0; nt < 4; nt++) {
                int cc = wn + nt * 8 + (lane & 3) * 2;
#pragma unroll
                for (int h = 0; h < 2; h++) {
                    int row = wm + mt * 16 + (lane >> 2) + h * 8;
                    float v0 = acc[mt][nt][h * 2], v1 = acc[mt][nt][h * 2 + 1];
                    __nv_bfloat16 h0, h1, l0, l1;
                    split_bf16(v0, h0, l0);
                    split_bf16(v1, h1, l1);
                    __nv_bfloat162 ph, pl;
                    ph.x = h0; ph.y = h1; pl.x = l0; pl.y = l1;
                    long o = (mBase + row) * D_E + cc;
                    *(__nv_bfloat162*)&dh[o] = ph;
                    *(__nv_bfloat162*)&dl[o] = pl;
                }
            }
    } else {
        // V: stage + transpose -> g_vth/g_vtl [n][d][t]
        float* stage = (float*)smc;  // 128 x 129 f32
#pragma unroll
        for (int mt = 0; mt < 4; mt++)
#pragma unroll
            for (int nt = 0; nt < 4; nt++) {
                int cc = wn + nt * 8 + (lane & 3) * 2;
#pragma unroll
                for (int h = 0; h < 2; h++) {
                    int row = wm + mt * 16 + (lane >> 2) + h * 8;
                    stage[row * 129 + cc] = acc[mt][nt][h * 2];
                    stage[row * 129 + cc + 1] = acc[mt][nt][h * 2 + 1];
                }
            }
        __syncthreads();
        int nb = (int)(mBase >> 12);
        int tb = (int)(mBase & (T_S - 1));
        for (int u = tid; u < 8192; u += 256) {
            int d = u >> 6, tp = (u & 63) * 2;
            float v0 = stage[tp * 129 + d];
            float v1 = stage[(tp + 1) * 129 + d];
            __nv_bfloat16 h0, h1, l0, l1;
            split_bf16(v0, h0, l0);
            split_bf16(v1, h1, l1);
            __nv_bfloat162 ph, pl;
            ph.x = h0; ph.y = h1; pl.x = l0; pl.y = l1;
            long o = ((long)nb * D_E + d) * T_S + tb + tp;
            *(__nv_bfloat162*)&g_vth[o] = ph;
            *(__nv_bfloat162*)&g_vtl[o] = pl;
        }
    }
}

// ============================================================
// K2: scores S = Q K^T, single-shot K=128 in smem, fused partial
// softmax stats. Pitch 272B. smem: Ah,Al,Bh,Bl @ 34816 ea + partials.
// ============================================================
#define SCP 272
#define SC_OP 34816

__global__ __launch_bounds__(256, 1) void scores_mma_kernel(float* __restrict__ att)
{
    int tri = blockIdx.x;
    int n = blockIdx.y;
    int i = (int)((sqrtf(8.f * tri + 1.f) - 1.f) * 0.5f);
    while ((i + 1) * (i + 2) / 2 <= tri) i++;
    while (i * (i + 1) / 2 > tri) i--;
    int j = tri - i * (i + 1) / 2;

    extern __shared__ char smc[];
    uint32_t sb = smem_u32(smc);
    int tid = threadIdx.x, lane = tid & 31, wid = tid >> 5;

    const __nv_bfloat16* sAh = g_qh + ((long)n * T_S + i * 128) * D_E;
    const __nv_bfloat16* sAl = g_ql + ((long)n * T_S + i * 128) * D_E;
    const __nv_bfloat16* sBh = g_kh + ((long)n * T_S + j * 128) * D_E;
    const __nv_bfloat16* sBl = g_kl + ((long)n * T_S + j * 128) * D_E;

    // single-shot load of all 4 operands (K=128)
    for (int u = tid; u < 8192; u += 256) {
        int arr = u >> 11, idx = u & 2047, row = idx >> 4, seg = idx & 15;
        const __nv_bfloat16* s =
            (arr == 0) ? sAh : (arr == 1) ? sAl : (arr == 2) ? sBh : sBl;
        CP16(sb + arr * SC_OP + row * SCP + seg * 16, s + (long)row * D_E + seg * 8);
    }
    CPCOMMIT();
    CPWAIT0();
    __syncthreads();

    int wm = (wid >> 2) * 64, wn = (wid & 3) * 32;
    float acc[4][4][4];
#pragma unroll
    for (int a = 0; a < 4; a++)
#pragma unroll
        for (int b = 0; b < 4; b++)
#pragma unroll
            for (int cc = 0; cc < 4; cc++) acc[a][b][cc] = 0.f;

#pragma unroll
    for (int ks = 0; ks < 8; ks++) {
        uint32_t ah[4][4], al[4][4], bh[4][2], bl[4][2];
        int arow = lane & 15;
        int acol = ks * 16 + (lane >> 4) * 8;
#pragma unroll
        for (int mt = 0; mt < 4; mt++) {
            uint32_t ro = (uint32_t)(wm + mt * 16 + arow) * SCP + acol * 2;
            ldsm_x4(ah[mt], sb + ro);
            ldsm_x4(al[mt], sb + SC_OP + ro);
        }
        int brow = lane & 7;
        int bcol = ks * 16 + ((lane >> 3) & 1) * 8;
#pragma unroll
        for (int nt = 0; nt < 4; nt++) {
            uint32_t ro = (uint32_t)(wn + nt * 8 + brow) * SCP + bcol * 2;
            ldsm_x2(bh[nt], sb + 2 * SC_OP + ro);
            ldsm_x2(bl[nt], sb + 3 * SC_OP + ro);
        }
#pragma unroll
        for (int mt = 0; mt < 4; mt++)
#pragma unroll
            for (int nt = 0; nt < 4; nt++) {
                mma_bf16(acc[mt][nt], ah[mt], bh[nt]);
                mma_bf16(acc[mt][nt], ah[mt], bl[nt]);
                mma_bf16(acc[mt][nt], al[mt], bh[nt]);
            }
    }

    // ---- epilogue: att write + fused partial softmax stats
    float* pm = (float*)(smc + 4 * SC_OP);        // [128][4]
    float* ps = pm + 512;                          // [128][4]
    float* attn = att + (long)n * T_S * T_S;
    float NI = neg_inf();

#pragma unroll
    for (int mt = 0; mt < 4; mt++)
#pragma unroll
        for (int h = 0; h < 2; h++) {
            int row = wm + mt * 16 + (lane >> 2) + h * 8;
            int tg = i * 128 + row;
            float vals[8];
            float m = NI;
#pragma unroll
            for (int nt = 0; nt < 4; nt++)
#pragma unroll
                for (int e = 0; e < 2; e++) {
                    int s = j * 128 + wn + nt * 8 + (lane & 3) * 2 + e;
                    float v = acc[mt][nt][h * 2 + e];
                    float ev;
                    if (s <= tg) {
                        ev = (v == 0.0f) ? NI : v;
                        attn[(long)tg * T_S + s] = ev;
                    } else {
                        ev = NI;
                    }
                    vals[nt * 2 + e] = ev;
                    m = fmaxf(m, ev);
                }
            m = fmaxf(m, __shfl_xor_sync(0xffffffffu, m, 1));
            m = fmaxf(m, __shfl_xor_sync(0xffffffffu, m, 2));
            float ssum = 0.f;
            if (m != NI) {
#pragma unroll
                for (int q = 0; q < 8; q++) ssum += __expf(vals[q] - m);
            }
            ssum += __shfl_xor_sync(0xffffffffu, ssum, 1);
            ssum += __shfl_xor_sync(0xffffffffu, ssum, 2);
            if ((lane & 3) == 0) {
                pm[row * 4 + (wid & 3)] = m;
                ps[row * 4 + (wid & 3)] = ssum;
            }
        }
    __syncthreads();

    if (tid < 128) {
        float m0 = pm[tid * 4], m1 = pm[tid * 4 + 1], m2 = pm[tid * 4 + 2], m3 = pm[tid * 4 + 3];
        float M = fmaxf(fmaxf(m0, m1), fmaxf(m2, m3));
        float S = 0.f;
        if (M != NI) {
            S = ps[tid * 4] * __expf(m0 - M) + ps[tid * 4 + 1] * __expf(m1 - M) +
                ps[tid * 4 + 2] * __expf(m2 - M) + ps[tid * 4 + 3] * __expf(m3 - M);
        }
        long o = ((long)n * T_S + i * 128 + tid) * 32 + j;
        g_pmax[o] = M;
        g_psum[o] = S;
    }
}

// ============================================================
// K3: combine partial stats -> g_rowmax/g_rowsum. One warp per row.
// ============================================================
__global__ void combine_kernel()
{
    int w = (blockIdx.x * blockDim.x + threadIdx.x) >> 5;
    int lane = threadIdx.x & 31;
    if (w >= NT) return;
    int t = w & (T_S - 1);
    int jmax = t >> 7;
    float NI = neg_inf();
    float m = NI, s = 0.f;
    if (lane <= jmax) {
        m = g_pmax[(long)w * 32 + lane];
        s = g_psum[(long)w * 32 + lane];
    }
    float M = m;
#pragma unroll
    for (int o = 16; o; o >>= 1) M = fmaxf(M, __shfl_xor_sync(0xffffffffu, M, o));
    float v = (m == NI) ? 0.f : s * __expf(m - M);
#pragma unroll
    for (int o = 16; o; o >>= 1) v += __shfl_xor_sync(0xffffffffu, v, o);
    if (lane == 0) {
        g_rowmax[w] = M;
        g_rowsum[w] = v;
    }
}

// ============================================================
// K4: split-K PV via mma.sync. A = P (exp on the fly, written back),
// B = vt bf16 hi/lo. grid (80, N_B).
// ============================================================
__global__ __launch_bounds__(256, 1) void pv_mma_kernel(float* __restrict__ att,
                                                        float* __restrict__ out)
{
    int b = blockIdx.x;
    int n = blockIdx.y;
    int i = 31, jg = 0;
    for (i = 31; i >= 0; --i) {
        int g = (i + 8) >> 3;
        if (b < g) { jg = b; break; }
        b -= g;
    }
    int ngroups = (i + 8) >> 3;
    int kStart = jg << 10;
    int kEndA = min((jg + 1) << 10, (i + 1) << 7);
    int nc = (kEndA - kStart) >> 5;

    extern __shared__ char smc[];
    uint32_t sb = smem_u32(smc);
    float* smax = (float*)(smc + 81920);
    float* sinv = (float*)(smc + 82432);
    int tid = threadIdx.x, lane = tid & 31, wid = tid >> 5;

    float* attn = att + (long)n * T_S * T_S;

    if (tid < 128) {
        int r = n * T_S + (i << 7) + tid;
        smax[tid] = g_rowmax[r];
        sinv[tid] = 1.f / g_rowsum[r];
    }
    __syncthreads();

    int wm = (wid >> 2) * 64, wn = (wid & 3) * 32;
    float acc[4][4][4];
#pragma unroll
    for (int a = 0; a < 4; a++)
#pragma unroll
        for (int b2 = 0; b2 < 4; b2++)
#pragma unroll
            for (int cc = 0; cc < 4; cc++) acc[a][b2][cc] = 0.f;

#define PV_LDB(c)                                                              \
    {                                                                          \
        int buf_ = (c) & 1;                                                    \
        int k0_ = kStart + (c) * 32;                                           \
        uint32_t db_ = sb + buf_ * 40960 + 20480;                              \
        for (int u = tid; u < 1024; u += 256) {                                \
            int arr = u >> 9, idx = u & 511, row = idx >> 2, seg = idx & 3;    \
            const __nv_bfloat16* s = (arr ? g_vtl : g_vth) +                   \
                ((long)n * D_E + row) * T_S + k0_ + seg * 8;                   \
            CP16(db_ + arr * 10240 + row * 80 + seg * 16, s);                  \
        }                                                                      \
        CPCOMMIT();                                                            \
    }

#define PV_LDA(c, ar)                                                          \
    {                                                                          \
        int k0_ = kStart + (c) * 32;                                           \
        _Pragma("unroll") for (int q = 0; q < 4; q++) {                        \
            int idx = tid + q * 256;                                           \
            int row = idx >> 3, seg = idx & 7;                                 \
            ar[q] = *(const float4*)&attn[(long)((i << 7) + row) * T_S + k0_ + seg * 4]; \
        }                                                                      \
    }

#define PV_PROC(c, ar)                                                         \
    {                                                                          \
        int k0_ = kStart + (c) * 32;                                           \
        _Pragma("unroll") for (int q = 0; q < 4; q++) {                        \
            int idx = tid + q * 256;                                           \
            int row = idx >> 3, seg = idx & 7;                                 \
            int t = (i << 7) + row;                                            \
            int s0 = k0_ + seg * 4;                                            \
            float rm = smax[row], ri = sinv[row];                              \
            float p0 = (s0 + 0 <= t) ? __expf(ar[q].x - rm) * ri : 0.f;        \
            float p1 = (s0 + 1 <= t) ? __expf(ar[q].y - rm) * ri : 0.f;        \
            float p2 = (s0 + 2 <= t) ? __expf(ar[q].z - rm) * ri : 0.f;        \
            float p3 = (s0 + 3 <= t) ? __expf(ar[q].w - rm) * ri : 0.f;        \
            *(float4*)&attn[(long)t * T_S + s0] = make_float4(p0, p1, p2, p3); \
            __nv_bfloat16 h0, h1, h2, h3, l0, l1, l2, l3;                      \
            split_bf16(p0, h0, l0); split_bf16(p1, h1, l1);                    \
            split_bf16(p2, h2, l2); split_bf16(p3, h3, l3);                    \
            __nv_bfloat162 ph0, ph1, pl0, pl1;                                 \
            ph0.x = h0; ph0.y = h1; ph1.x = h2; ph1.y = h3;                    \
            pl0.x = l0; pl0.y = l1; pl1.x = l2; pl1.y = l3;                    \
            uint32_t so = row * 80 + seg * 8;                                  \
            *(uint2*)(smc + (((c) & 1) * 40960) + so) =                        \
                make_uint2(*(uint32_t*)&ph0, *(uint32_t*)&ph1);                \
            *(uint2*)(smc + (((c) & 1) * 40960) + 10240 + so) =                \
                make_uint2(*(uint32_t*)&pl0, *(uint32_t*)&pl1);                \
        }                                                                      \
    }

    float4 arA[4], arN[4];
    PV_LDB(0);
    PV_LDA(0, arA);
    PV_PROC(0, arA);

    for (int c = 0; c < nc; c++) {
        if (c + 1 < nc) {
            PV_LDB(c + 1);
            PV_LDA(c + 1, arN);
            CPWAIT1();
        } else {
            CPWAIT0();
        }
        __syncthreads();
        mma_tile_step(sb, c & 1, 0, wm, wn, lane, acc);
        mma_tile_step(sb, c & 1, 1, wm, wn, lane, acc);
        if (c + 1 < nc) PV_PROC(c + 1, arN);
        __syncthreads();
    }
#undef PV_LDB
#undef PV_LDA
#undef PV_PROC

    float* dst;
    if (ngroups == 1) dst = out + ((long)n * T_S + (i << 7)) * D_E;
    else dst = g_part + (((long)(n * 24 + (i - 8)) * 4 + jg) << 14);
#pragma unroll
    for (int mt = 0; mt < 4; mt++)
#pragma unroll
        for (int nt = 0; nt < 4; nt++) {
            int cc = wn + nt * 8 + (lane & 3) * 2;
#pragma unroll
            for (int h = 0; h < 2; h++) {
                int row = wm + mt * 16 + (lane >> 2) + h * 8;
                *(float2*)&dst[(long)row * 128 + cc] =
                    make_float2(acc[mt][nt][h * 2], acc[mt][nt][h * 2 + 1]);
            }
        }

    if (jg == ngroups - 1) {
        int zstart = (i + 1) << 7;
        int Wd = T_S - zstart;
        if (Wd > 0) {
            long Z = (long)128 * Wd;
            float4 z = make_float4(0.f, 0.f, 0.f, 0.f);
            for (long e = (long)tid * 4; e < Z; e += 1024) {
                int row = (int)(e / Wd);
                int col = (int)(e % Wd);
                *(float4*)&attn[(long)((i << 7) + row) * T_S + zstart + col] = z;
            }
        }
    }
}

// ============================================================
// K5: reduce split-K partials
// ============================================================
__global__ void reduce_kernel(float* __restrict__ out)
{
    int ii = blockIdx.x;
    int n = blockIdx.y;
    int i = ii + 8;
    int ng = (i + 8) >> 3;
    const float* base = g_part + (((long)(n * 24 + ii) * 4) << 14);
    float* o = out + ((long)n * T_S + (i << 7)) * D_E;
    for (int e = threadIdx.x * 4; e < 128 * 128; e += 1024) {
        float4 s = *(const float4*)&base[e];
        for (int g = 1; g < ng; g++) {
            float4 p = *(const float4*)&base[((long)g << 14) + e];
            s.x += p.x; s.y += p.y; s.z += p.z; s.w += p.w;
        }
        *(float4*)&o[e] = s;
    }
}

// ============================================================
extern "C" void kernel_launch(void* const* d_in, const int* in_sizes, int n_in,
                              void* d_out, int out_size)
{
    const float* x  = (const float*)d_in[0];
    const float* Wq = (const float*)d_in[1];
    const float* Wk = (const float*)d_in[2];
    const float* Wv = (const float*)d_in[3];

    const long NTD = (long)NT * D_E;
    const long NTT = (long)N_B * T_S * T_S;

    float* dout = (float*)d_out;
    float* out_ptr;
    float* att_ptr;
    if ((long)out_size >= NTD + NTT) {
        out_ptr = dout;
        att_ptr = dout + NTD;
    } else if ((long)out_size == NTT) {
        att_ptr = dout;
        void* fb = nullptr;
        cudaGetSymbolAddress(&fb, g_out_fallback);
        out_ptr = (float*)fb;
    } else {
        out_ptr = dout;
        att_ptr = dout;
    }

    cudaFuncSetAttribute(qkv_mma_kernel, cudaFuncAttributeMaxDynamicSharedMemorySize, 81920);
    cudaFuncSetAttribute(scores_mma_kernel, cudaFuncAttributeMaxDynamicSharedMemorySize, 143360);
    cudaFuncSetAttribute(pv_mma_kernel, cudaFuncAttributeMaxDynamicSharedMemorySize, 82944);

    splitx_kernel<<<(long)NT * DIN / 1024, 256>>>(x);
    wt_kernel<<<dim3(DIN / 32, D_E / 32, 3), 256>>>(Wq, Wk, Wv);

    qkv_mma_kernel<<<dim3(NT / 128, 3), 256, 81920>>>();

    int nTiles = T_S / 128;
    int nTri = nTiles * (nTiles + 1) / 2;
    scores_mma_kernel<<<dim3(nTri, N_B), 256, 143360>>>(att_ptr);

    combine_kernel<<<NT / 8, 256>>>();

    pv_mma_kernel<<<dim3(80, N_B), 256, 82944>>>(att_ptr, out_ptr);

    reduce_kernel<<<dim3(24, N_B), 256>>>(out_ptr);
}

// round 7
// speedup vs baseline: 3.2097x; 1.0675x over previous
#include <cuda_runtime.h>
#include <cuda_bf16.h>
#include <math.h>
#include <stdint.h>

#define N_B 4
#define T_S 4096
#define DIN 1024
#define D_E 128
#define NT (N_B * T_S)
#define PCH 40      // smem row pitch in halfs (32 + 8 pad)
#define BUFSZ 40960 // one ring-stage: 4 regions x 10240B
#define XTRA 4096   // epilogue scratch after the ring

// ---- scratch (device globals: allocation-free) ----
__device__ __nv_bfloat16 g_xh[(long)NT * DIN];
__device__ __nv_bfloat16 g_xl[(long)NT * DIN];
__device__ __nv_bfloat16 g_wth[3 * D_E * DIN];
__device__ __nv_bfloat16 g_wtl[3 * D_E * DIN];
__device__ __nv_bfloat16 g_qh[NT * D_E];
__device__ __nv_bfloat16 g_ql[NT * D_E];
__device__ __nv_bfloat16 g_kh[NT * D_E];
__device__ __nv_bfloat16 g_kl[NT * D_E];
__device__ __nv_bfloat16 g_vth[(long)N_B * D_E * T_S];
__device__ __nv_bfloat16 g_vtl[(long)N_B * D_E * T_S];
__device__ float g_pmax[(long)NT * 32];
__device__ float g_psum[(long)NT * 32];
__device__ float g_rowmax[NT];
__device__ float g_rowsum[NT];
__device__ float g_part[(long)4 * 24 * 4 * 128 * 128];
__device__ float g_out_fallback[NT * D_E];

__device__ __forceinline__ float neg_inf() { return __int_as_float(0xff800000); }

__device__ __forceinline__ uint32_t smem_u32(const void* p) {
    uint32_t a;
    asm("{ .reg .u64 t; cvta.to.shared.u64 t, %1; cvt.u32.u64 %0, t; }" : "=r"(a) : "l"(p));
    return a;
}
__device__ __forceinline__ void split_bf16(float x, __nv_bfloat16& h, __nv_bfloat16& l) {
    h = __float2bfloat16(x);
    l = __float2bfloat16(x - __bfloat162float(h));
}

#define CP16(dst, src) asm volatile("cp.async.cg.shared.global [%0], [%1], 16;" :: "r"(dst), "l"(src))
#define CPCOMMIT() asm volatile("cp.async.commit_group;" ::: "memory")
#define CPWAIT1() asm volatile("cp.async.wait_group 1;" ::: "memory")
#define CPWAIT0() asm volatile("cp.async.wait_group 0;" ::: "memory")

__device__ __forceinline__ void ldsm_x4(uint32_t* r, uint32_t addr) {
    asm volatile("ldmatrix.sync.aligned.m8n8.x4.shared.b16 {%0,%1,%2,%3}, [%4];"
        : "=r"(r[0]), "=r"(r[1]), "=r"(r[2]), "=r"(r[3]) : "r"(addr));
}
__device__ __forceinline__ void ldsm_x2(uint32_t* r, uint32_t addr) {
    asm volatile("ldmatrix.sync.aligned.m8n8.x2.shared.b16 {%0,%1}, [%2];"
        : "=r"(r[0]), "=r"(r[1]) : "r"(addr));
}
__device__ __forceinline__ void mma_bf16(float* c, const uint32_t* a, const uint32_t* b) {
    asm volatile(
        "mma.sync.aligned.m16n8k16.row.col.f32.bf16.bf16.f32 "
        "{%0,%1,%2,%3}, {%4,%5,%6,%7}, {%8,%9}, {%0,%1,%2,%3};"
        : "+f"(c[0]), "+f"(c[1]), "+f"(c[2]), "+f"(c[3])
        : "r"(a[0]), "r"(a[1]), "r"(a[2]), "r"(a[3]), "r"(b[0]), "r"(b[1]));
}

// One k16 step of the 64x32 warp tile, bf16-split (3 mma per frag pair).
// Ring-stage layout: Ah@0, Al@10240, Bh@20480, Bl@30720 (bytes), pitch PCH halfs.
__device__ __forceinline__ void mma_tile_step3(uint32_t sb, int buf, int ks,
                                               int wm, int wn, int lane,
                                               float (*acc)[4][4])
{
    uint32_t base = sb + buf * BUFSZ;
    uint32_t ah[4][4], al[4][4], bh[4][2], bl[4][2];
    int arow = lane & 15;
    int acol = ks * 16 + (lane >> 4) * 8;
#pragma unroll
    for (int mt = 0; mt < 4; mt++) {
        uint32_t ro = (uint32_t)(wm + mt * 16 + arow) * (PCH * 2) + acol * 2;
        ldsm_x4(ah[mt], base + ro);
        ldsm_x4(al[mt], base + 10240 + ro);
    }
    int brow = lane & 7;
    int bcol = ks * 16 + ((lane >> 3) & 1) * 8;
#pragma unroll
    for (int nt = 0; nt < 4; nt++) {
        uint32_t ro = (uint32_t)(wn + nt * 8 + brow) * (PCH * 2) + bcol * 2;
        ldsm_x2(bh[nt], base + 20480 + ro);
        ldsm_x2(bl[nt], base + 30720 + ro);
    }
#pragma unroll
    for (int mt = 0; mt < 4; mt++)
#pragma unroll
        for (int nt = 0; nt < 4; nt++) {
            mma_bf16(acc[mt][nt], ah[mt], bh[nt]);
            mma_bf16(acc[mt][nt], ah[mt], bl[nt]);
            mma_bf16(acc[mt][nt], al[mt], bh[nt]);
        }
}

// ============================================================
// K-1: split x into bf16 hi/lo
// ============================================================
__global__ __launch_bounds__(256) void splitx_kernel(const float* __restrict__ x)
{
    long idx = ((long)blockIdx.x * 256 + threadIdx.x) * 4;
    float4 a = *(const float4*)&x[idx];
    __nv_bfloat16 h0, h1, h2, h3, l0, l1, l2, l3;
    split_bf16(a.x, h0, l0);
    split_bf16(a.y, h1, l1);
    split_bf16(a.z, h2, l2);
    split_bf16(a.w, h3, l3);
    __nv_bfloat162 ph0, ph1, pl0, pl1;
    ph0.x = h0; ph0.y = h1; ph1.x = h2; ph1.y = h3;
    pl0.x = l0; pl0.y = l1; pl1.x = l2; pl1.y = l3;
    *(uint2*)&g_xh[idx] = make_uint2(*(uint32_t*)&ph0, *(uint32_t*)&ph1);
    *(uint2*)&g_xl[idx] = make_uint2(*(uint32_t*)&pl0, *(uint32_t*)&pl1);
}

// ============================================================
// K0: transpose + split W
// ============================================================
__global__ __launch_bounds__(256) void wt_kernel(const float* __restrict__ Wq,
                                                 const float* __restrict__ Wk,
                                                 const float* __restrict__ Wv)
{
    const float* W = (blockIdx.z == 0) ? Wq : ((blockIdx.z == 1) ? Wk : Wv);
    __shared__ float t[32][33];
    int tid = threadIdx.x;
    int tx = tid & 31, ty = tid >> 5;
    int k0 = blockIdx.x * 32, n0 = blockIdx.y * 32;
#pragma unroll
    for (int s = 0; s < 4; s++) t[ty + s * 8][tx] = W[(k0 + ty + s * 8) * D_E + n0 + tx];
    __syncthreads();
    long wb = (long)blockIdx.z * D_E * DIN;
#pragma unroll
    for (int s = 0; s < 4; s++) {
        int n = n0 + ty + s * 8, k = k0 + tx;
        __nv_bfloat16 h, l;
        split_bf16(t[tx][ty + s * 8], h, l);
        g_wth[wb + (long)n * DIN + k] = h;
        g_wtl[wb + (long)n * DIN + k] = l;
    }
}

// ============================================================
// K1: QKV via mma.sync, 3-stage ring, 1 sync/chunk. grid (NT/128, 3)
// ============================================================
__global__ __launch_bounds__(256, 1) void qkv_mma_kernel()
{
    extern __shared__ char smc[];
    uint32_t sb = smem_u32(smc);
    int tid = threadIdx.x, lane = tid & 31, wid = tid >> 5;
    int w = blockIdx.y;
    long mBase = (long)blockIdx.x * 128;

    const __nv_bfloat16* sAh = g_xh + mBase * DIN;
    const __nv_bfloat16* sAl = g_xl + mBase * DIN;
    const __nv_bfloat16* sBh = g_wth + (long)w * D_E * DIN;
    const __nv_bfloat16* sBl = g_wtl + (long)w * D_E * DIN;

    int wm = (wid >> 2) * 64, wn = (wid & 3) * 32;
    float acc[4][4][4];
#pragma unroll
    for (int a = 0; a < 4; a++)
#pragma unroll
        for (int b = 0; b < 4; b++)
#pragma unroll
            for (int cc = 0; cc < 4; cc++) acc[a][b][cc] = 0.f;

#define QKV_LOAD(c, bf)                                                        \
    {                                                                          \
        int k0_ = (c) * 32;                                                    \
        uint32_t db_ = sb + (bf) * BUFSZ;                                      \
        for (int u = tid; u < 2048; u += 256) {                                \
            int arr = u >> 9, idx = u & 511, row = idx >> 2, seg = idx & 3;    \
            const __nv_bfloat16* s =                                           \
                (arr == 0) ? sAh : (arr == 1) ? sAl : (arr == 2) ? sBh : sBl;  \
            CP16(db_ + arr * 10240 + row * 80 + seg * 16,                      \
                 s + (long)row * DIN + k0_ + seg * 8);                         \
        }                                                                      \
        CPCOMMIT();                                                            \
    }

    QKV_LOAD(0, 0);
    QKV_LOAD(1, 1);
    int bm = 0, blb = 2;
    for (int c = 0; c < 32; c++) {
        if (c < 31) { CPWAIT1(); } else { CPWAIT0(); }
        __syncthreads();
        if (c + 2 < 32) QKV_LOAD(c + 2, blb);
        mma_tile_step3(sb, bm, 0, wm, wn, lane, acc);
        mma_tile_step3(sb, bm, 1, wm, wn, lane, acc);
        bm = (bm == 2) ? 0 : bm + 1;
        blb = (blb == 2) ? 0 : blb + 1;
    }
#undef QKV_LOAD
    __syncthreads();

    if (w < 2) {
        __nv_bfloat16* dh = w ? g_kh : g_qh;
        __nv_bfloat16* dl = w ? g_kl : g_ql;
#pragma unroll
        for (int mt = 0; mt < 4; mt++)
#pragma unroll
            for (int nt = 0; nt < 4; nt++) {
                int cc = wn + nt * 8 + (lane & 3) * 2;
#pragma unroll
                for (int h = 0; h < 2; h++) {
                    int row = wm + mt * 16 + (lane >> 2) + h * 8;
                    float v0 = acc[mt][nt][h * 2], v1 = acc[mt][nt][h * 2 + 1];
                    __nv_bfloat16 h0, h1, l0, l1;
                    split_bf16(v0, h0, l0);
                    split_bf16(v1, h1, l1);
                    __nv_bfloat162 ph, pl;
                    ph.x = h0; ph.y = h1; pl.x = l0; pl.y = l1;
                    long o = (mBase + row) * D_E + cc;
                    *(__nv_bfloat162*)&dh[o] = ph;
                    *(__nv_bfloat162*)&dl[o] = pl;
                }
            }
    } else {
        float* stage = (float*)smc;  // 128 x 129 f32 = 66048B < 3*BUFSZ
#pragma unroll
        for (int mt = 0; mt < 4; mt++)
#pragma unroll
            for (int nt = 0; nt < 4; nt++) {
                int cc = wn + nt * 8 + (lane & 3) * 2;
#pragma unroll
                for (int h = 0; h < 2; h++) {
                    int row = wm + mt * 16 + (lane >> 2) + h * 8;
                    stage[row * 129 + cc] = acc[mt][nt][h * 2];
                    stage[row * 129 + cc + 1] = acc[mt][nt][h * 2 + 1];
                }
            }
        __syncthreads();
        int nb = (int)(mBase >> 12);
        int tb = (int)(mBase & (T_S - 1));
        for (int u = tid; u < 8192; u += 256) {
            int d = u >> 6, tp = (u & 63) * 2;
            float v0 = stage[tp * 129 + d];
            float v1 = stage[(tp + 1) * 129 + d];
            __nv_bfloat16 h0, h1, l0, l1;
            split_bf16(v0, h0, l0);
            split_bf16(v1, h1, l1);
            __nv_bfloat162 ph, pl;
            ph.x = h0; ph.y = h1; pl.x = l0; pl.y = l1;
            long o = ((long)nb * D_E + d) * T_S + tb + tp;
            *(__nv_bfloat162*)&g_vth[o] = ph;
            *(__nv_bfloat162*)&g_vtl[o] = pl;
        }
    }
}

// ============================================================
// K2: scores S = Q K^T, 3-stage ring pipeline + fused partial stats.
// ============================================================
__global__ __launch_bounds__(256, 1) void scores_mma_kernel(float* __restrict__ att)
{
    int tri = blockIdx.x;
    int n = blockIdx.y;
    int i = (int)((sqrtf(8.f * tri + 1.f) - 1.f) * 0.5f);
    while ((i + 1) * (i + 2) / 2 <= tri) i++;
    while (i * (i + 1) / 2 > tri) i--;
    int j = tri - i * (i + 1) / 2;

    extern __shared__ char smc[];
    uint32_t sb = smem_u32(smc);
    int tid = threadIdx.x, lane = tid & 31, wid = tid >> 5;

    const __nv_bfloat16* sAh = g_qh + ((long)n * T_S + i * 128) * D_E;
    const __nv_bfloat16* sAl = g_ql + ((long)n * T_S + i * 128) * D_E;
    const __nv_bfloat16* sBh = g_kh + ((long)n * T_S + j * 128) * D_E;
    const __nv_bfloat16* sBl = g_kl + ((long)n * T_S + j * 128) * D_E;

    int wm = (wid >> 2) * 64, wn = (wid & 3) * 32;
    float acc[4][4][4];
#pragma unroll
    for (int a = 0; a < 4; a++)
#pragma unroll
        for (int b = 0; b < 4; b++)
#pragma unroll
            for (int cc = 0; cc < 4; cc++) acc[a][b][cc] = 0.f;

#define SC_LOAD(c, bf)                                                         \
    {                                                                          \
        int k0_ = (c) * 32;                                                    \
        uint32_t db_ = sb + (bf) * BUFSZ;                                      \
        for (int u = tid; u < 2048; u += 256) {                                \
            int arr = u >> 9, idx = u & 511, row = idx >> 2, seg = idx & 3;    \
            const __nv_bfloat16* s =                                           \
                (arr == 0) ? sAh : (arr == 1) ? sAl : (arr == 2) ? sBh : sBl;  \
            CP16(db_ + arr * 10240 + row * 80 + seg * 16,                      \
                 s + (long)row * D_E + k0_ + seg * 8);                         \
        }                                                                      \
        CPCOMMIT();                                                            \
    }

    SC_LOAD(0, 0);
    SC_LOAD(1, 1);
#pragma unroll
    for (int c = 0; c < 4; c++) {
        if (c < 3) { CPWAIT1(); } else { CPWAIT0(); }
        __syncthreads();
        if (c + 2 < 4) SC_LOAD(c + 2, (c + 2) % 3);
        mma_tile_step3(sb, c % 3, 0, wm, wn, lane, acc);
        mma_tile_step3(sb, c % 3, 1, wm, wn, lane, acc);
    }
#undef SC_LOAD

    // ---- epilogue: att write + fused partial softmax stats (two-pass)
    float* pm = (float*)(smc + 3 * BUFSZ);  // [128][4] = 2048B
    float* ps = pm + 512;                   // [128][4] = 2048B  (total 4096 <= XTRA)
    float* attn = att + (long)n * T_S * T_S;
    float NI = neg_inf();

#pragma unroll
    for (int mt = 0; mt < 4; mt++)
#pragma unroll
        for (int h = 0; h < 2; h++) {
            int row = wm + mt * 16 + (lane >> 2) + h * 8;
            int tg = i * 128 + row;
            float m = NI;
#pragma unroll
            for (int nt = 0; nt < 4; nt++)
#pragma unroll
                for (int e = 0; e < 2; e++) {
                    int s = j * 128 + wn + nt * 8 + (lane & 3) * 2 + e;
                    if (s <= tg) {
                        float v = acc[mt][nt][h * 2 + e];
                        float ev = (v == 0.0f) ? NI : v;
                        attn[(long)tg * T_S + s] = ev;
                        m = fmaxf(m, ev);
                    }
                }
            m = fmaxf(m, __shfl_xor_sync(0xffffffffu, m, 1));
            m = fmaxf(m, __shfl_xor_sync(0xffffffffu, m, 2));
            float ssum = 0.f;
            if (m != NI) {
#pragma unroll
                for (int nt = 0; nt < 4; nt++)
#pragma unroll
                    for (int e = 0; e < 2; e++) {
                        int s = j * 128 + wn + nt * 8 + (lane & 3) * 2 + e;
                        if (s <= tg) {
                            float v = acc[mt][nt][h * 2 + e];
                            float ev = (v == 0.0f) ? NI : v;
                            ssum += __expf(ev - m);
                        }
                    }
            }
            ssum += __shfl_xor_sync(0xffffffffu, ssum, 1);
            ssum += __shfl_xor_sync(0xffffffffu, ssum, 2);
            if ((lane & 3) == 0) {
                pm[row * 4 + (wid & 3)] = m;
                ps[row * 4 + (wid & 3)] = ssum;
            }
        }
    __syncthreads();

    if (tid < 128) {
        float m0 = pm[tid * 4], m1 = pm[tid * 4 + 1], m2 = pm[tid * 4 + 2], m3 = pm[tid * 4 + 3];
        float M = fmaxf(fmaxf(m0, m1), fmaxf(m2, m3));
        float S = 0.f;
        if (M != NI) {
            S = ps[tid * 4] * __expf(m0 - M) + ps[tid * 4 + 1] * __expf(m1 - M) +
                ps[tid * 4 + 2] * __expf(m2 - M) + ps[tid * 4 + 3] * __expf(m3 - M);
        }
        long o = ((long)n * T_S + i * 128 + tid) * 32 + j;
        g_pmax[o] = M;
        g_psum[o] = S;
    }
}

// ============================================================
// K3: combine partial stats -> g_rowmax/g_rowsum. One warp per row.
// ============================================================
__global__ void combine_kernel()
{
    int w = (blockIdx.x * blockDim.x + threadIdx.x) >> 5;
    int lane = threadIdx.x & 31;
    if (w >= NT) return;
    int t = w & (T_S - 1);
    int jmax = t >> 7;
    float NI = neg_inf();
    float m = NI, s = 0.f;
    if (lane <= jmax) {
        m = g_pmax[(long)w * 32 + lane];
        s = g_psum[(long)w * 32 + lane];
    }
    float M = m;
#pragma unroll
    for (int o = 16; o; o >>= 1) M = fmaxf(M, __shfl_xor_sync(0xffffffffu, M, o));
    float v = (m == NI) ? 0.f : s * __expf(m - M);
#pragma unroll
    for (int o = 16; o; o >>= 1) v += __shfl_xor_sync(0xffffffffu, v, o);
    if (lane == 0) {
        g_rowmax[w] = M;
        g_rowsum[w] = v;
    }
}

// ============================================================
// K4: split-K PV, 3-stage ring, 1 sync/chunk. grid (80, N_B).
// ============================================================
__global__ __launch_bounds__(256, 1) void pv_mma_kernel(float* __restrict__ att,
                                                        float* __restrict__ out)
{
    int b = blockIdx.x;
    int n = blockIdx.y;
    int i = 31, jg = 0;
    for (i = 31; i >= 0; --i) {
        int g = (i + 8) >> 3;
        if (b < g) { jg = b; break; }
        b -= g;
    }
    int ngroups = (i + 8) >> 3;
    int kStart = jg << 10;
    int kEndA = min((jg + 1) << 10, (i + 1) << 7);
    int nc = (kEndA - kStart) >> 5;

    extern __shared__ char smc[];
    uint32_t sb = smem_u32(smc);
    float* smax = (float*)(smc + 3 * BUFSZ);  // 512B
    float* sinv = smax + 128;                 // 512B (total 1024 <= XTRA)
    int tid = threadIdx.x, lane = tid & 31, wid = tid >> 5;

    float* attn = att + (long)n * T_S * T_S;

    if (tid < 128) {
        int r = n * T_S + (i << 7) + tid;
        smax[tid] = g_rowmax[r];
        sinv[tid] = 1.f / g_rowsum[r];
    }
    __syncthreads();

    int wm = (wid >> 2) * 64, wn = (wid & 3) * 32;
    float acc[4][4][4];
#pragma unroll
    for (int a = 0; a < 4; a++)
#pragma unroll
        for (int b2 = 0; b2 < 4; b2++)
#pragma unroll
            for (int cc = 0; cc < 4; cc++) acc[a][b2][cc] = 0.f;

#define PV_LDB(c, bf)                                                          \
    {                                                                          \
        int k0_ = kStart + (c) * 32;                                           \
        uint32_t db_ = sb + (bf) * BUFSZ + 20480;                              \
        for (int u = tid; u < 1024; u += 256) {                                \
            int arr = u >> 9, idx = u & 511, row = idx >> 2, seg = idx & 3;    \
            const __nv_bfloat16* s = (arr ? g_vtl : g_vth) +                   \
                ((long)n * D_E + row) * T_S + k0_ + seg * 8;                   \
            CP16(db_ + arr * 10240 + row * 80 + seg * 16, s);                  \
        }                                                                      \
        CPCOMMIT();                                                            \
    }

#define PV_LDA(c, ar)                                                          \
    {                                                                          \
        int k0_ = kStart + (c) * 32;                                           \
        _Pragma("unroll") for (int q = 0; q < 4; q++) {                        \
            int idx = tid + q * 256;                                           \
            int row = idx >> 3, seg = idx & 7;                                 \
            ar[q] = *(const float4*)&attn[(long)((i << 7) + row) * T_S + k0_ + seg * 4]; \
        }                                                                      \
    }

#define PV_PROC(c, ar, bf)                                                     \
    {                                                                          \
        int k0_ = kStart + (c) * 32;                                           \
        _Pragma("unroll") for (int q = 0; q < 4; q++) {                        \
            int idx = tid + q * 256;                                           \
            int row = idx >> 3, seg = idx & 7;                                 \
            int t = (i << 7) + row;                                            \
            int s0 = k0_ + seg * 4;                                            \
            float rm = smax[row], ri = sinv[row];                              \
            float p0 = (s0 + 0 <= t) ? __expf(ar[q].x - rm) * ri : 0.f;        \
            float p1 = (s0 + 1 <= t) ? __expf(ar[q].y - rm) * ri : 0.f;        \
            float p2 = (s0 + 2 <= t) ? __expf(ar[q].z - rm) * ri : 0.f;        \
            float p3 = (s0 + 3 <= t) ? __expf(ar[q].w - rm) * ri : 0.f;        \
            *(float4*)&attn[(long)t * T_S + s0] = make_float4(p0, p1, p2, p3); \
            __nv_bfloat16 h0, h1, h2, h3, l0, l1, l2, l3;                      \
            split_bf16(p0, h0, l0); split_bf16(p1, h1, l1);                    \
            split_bf16(p2, h2, l2); split_bf16(p3, h3, l3);                    \
            __nv_bfloat162 ph0, ph1, pl0, pl1;                                 \
            ph0.x = h0; ph0.y = h1; ph1.x = h2; ph1.y = h3;                    \
            pl0.x = l0; pl0.y = l1; pl1.x = l2; pl1.y = l3;                    \
            uint32_t so = row * 80 + seg * 8;                                  \
            *(uint2*)(smc + (bf) * BUFSZ + so) =                               \
                make_uint2(*(uint32_t*)&ph0, *(uint32_t*)&ph1);                \
            *(uint2*)(smc + (bf) * BUFSZ + 10240 + so) =                       \
                make_uint2(*(uint32_t*)&pl0, *(uint32_t*)&pl1);                \
        }                                                                      \
    }

    float4 ar[4];
    PV_LDB(0, 0);
    PV_LDB(1, 1);
    PV_LDA(0, ar);
    PV_PROC(0, ar, 0);

    int bm = 0, blb = 2, bp = 1;
    for (int c = 0; c < nc; c++) {
        if (c < nc - 1) { CPWAIT1(); } else { CPWAIT0(); }
        __syncthreads();
        if (c + 2 < nc) PV_LDB(c + 2, blb);
        if (c + 1 < nc) PV_LDA(c + 1, ar);
        mma_tile_step3(sb, bm, 0, wm, wn, lane, acc);
        mma_tile_step3(sb, bm, 1, wm, wn, lane, acc);
        if (c + 1 < nc) PV_PROC(c + 1, ar, bp);
        bm = (bm == 2) ? 0 : bm + 1;
        blb = (blb == 2) ? 0 : blb + 1;
        bp = (bp == 2) ? 0 : bp + 1;
    }
#undef PV_LDB
#undef PV_LDA
#undef PV_PROC

    float* dst;
    if (ngroups == 1) dst = out + ((long)n * T_S + (i << 7)) * D_E;
    else dst = g_part + (((long)(n * 24 + (i - 8)) * 4 + jg) << 14);
#pragma unroll
    for (int mt = 0; mt < 4; mt++)
#pragma unroll
        for (int nt = 0; nt < 4; nt++) {
            int cc = wn + nt * 8 + (lane & 3) * 2;
#pragma unroll
            for (int h = 0; h < 2; h++) {
                int row = wm + mt * 16 + (lane >> 2) + h * 8;
                *(float2*)&dst[(long)row * 128 + cc] =
                    make_float2(acc[mt][nt][h * 2], acc[mt][nt][h * 2 + 1]);
            }
        }

    // zero-fill att above band (last group), div-free
    if (jg == ngroups - 1) {
        int zstart = (i + 1) << 7;
        if (zstart < T_S) {
            float4 z = make_float4(0.f, 0.f, 0.f, 0.f);
            for (int row = wid; row < 128; row += 8) {
                float* rp = attn + (long)((i << 7) + row) * T_S;
                for (int cc = zstart + lane * 4; cc < T_S; cc += 128)
                    *(float4*)&rp[cc] = z;
            }
        }
    }
}

// ============================================================
// K5: reduce split-K partials
// ============================================================
__global__ void reduce_kernel(float* __restrict__ out)
{
    int ii = blockIdx.x;
    int n = blockIdx.y;
    int i = ii + 8;
    int ng = (i + 8) >> 3;
    const float* base = g_part + (((long)(n * 24 + ii) * 4) << 14);
    float* o = out + ((long)n * T_S + (i << 7)) * D_E;
    for (int e = threadIdx.x * 4; e < 128 * 128; e += 1024) {
        float4 s = *(const float4*)&base[e];
        for (int g = 1; g < ng; g++) {
            float4 p = *(const float4*)&base[((long)g << 14) + e];
            s.x += p.x; s.y += p.y; s.z += p.z; s.w += p.w;
        }
        *(float4*)&o[e] = s;
    }
}

// ============================================================
extern "C" void kernel_launch(void* const* d_in, const int* in_sizes, int n_in,
                              void* d_out, int out_size)
{
    const float* x  = (const float*)d_in[0];
    const float* Wq = (const float*)d_in[1];
    const float* Wk = (const float*)d_in[2];
    const float* Wv = (const float*)d_in[3];

    const long NTD = (long)NT * D_E;
    const long NTT = (long)N_B * T_S * T_S;

    float* dout = (float*)d_out;
    float* out_ptr;
    float* att_ptr;
    if ((long)out_size >= NTD + NTT) {
        out_ptr = dout;
        att_ptr = dout + NTD;
    } else if ((long)out_size == NTT) {
        att_ptr = dout;
        void* fb = nullptr;
        cudaGetSymbolAddress(&fb, g_out_fallback);
        out_ptr = (float*)fb;
    } else {
        out_ptr = dout;
        att_ptr = dout;
    }

    cudaFuncSetAttribute(qkv_mma_kernel, cudaFuncAttributeMaxDynamicSharedMemorySize, 3 * BUFSZ + XTRA);
    cudaFuncSetAttribute(scores_mma_kernel, cudaFuncAttributeMaxDynamicSharedMemorySize, 3 * BUFSZ + XTRA);
    cudaFuncSetAttribute(pv_mma_kernel, cudaFuncAttributeMaxDynamicSharedMemorySize, 3 * BUFSZ + XTRA);

    splitx_kernel<<<(long)NT * DIN / 1024, 256>>>(x);
    wt_kernel<<<dim3(DIN / 32, D_E / 32, 3), 256>>>(Wq, Wk, Wv);

    qkv_mma_kernel<<<dim3(NT / 128, 3), 256, 3 * BUFSZ + XTRA>>>();

    int nTiles = T_S / 128;
    int nTri = nTiles * (nTiles + 1) / 2;
    scores_mma_kernel<<<dim3(nTri, N_B), 256, 3 * BUFSZ + XTRA>>>(att_ptr);

    combine_kernel<<<NT / 8, 256>>>();

    pv_mma_kernel<<<dim3(80, N_B), 256, 3 * BUFSZ + XTRA>>>(att_ptr, out_ptr);

    reduce_kernel<<<dim3(24, N_B), 256>>>(out_ptr);
}

// round 8
// speedup vs baseline: 3.4934x; 1.0884x over previous
#include <cuda_runtime.h>
#include <cuda_bf16.h>
#include <math.h>
#include <stdint.h>

#define N_B 4
#define T_S 4096
#define DIN 1024
#define D_E 128
#define NT (N_B * T_S)
#define PCH 40      // smem row pitch in halfs (32 + 8 pad)
#define BUFSZ 40960 // one stage: 4 regions x 10240B

// ---- scratch (device globals: allocation-free) ----
__device__ __nv_bfloat16 g_xh[(long)NT * DIN];
__device__ __nv_bfloat16 g_xl[(long)NT * DIN];
__device__ __nv_bfloat16 g_wth[3 * D_E * DIN];
__device__ __nv_bfloat16 g_wtl[3 * D_E * DIN];
__device__ __nv_bfloat16 g_qh[NT * D_E];
__device__ __nv_bfloat16 g_ql[NT * D_E];
__device__ __nv_bfloat16 g_kh[NT * D_E];
__device__ __nv_bfloat16 g_kl[NT * D_E];
__device__ __nv_bfloat16 g_vth[(long)N_B * D_E * T_S];
__device__ __nv_bfloat16 g_vtl[(long)N_B * D_E * T_S];
__device__ float g_pmax[(long)NT * 32];
__device__ float g_psum[(long)NT * 32];
__device__ float g_rowmax[NT];
__device__ float g_rowsum[NT];
__device__ float g_part[(long)4 * 24 * 4 * 128 * 128];
__device__ float g_out_fallback[NT * D_E];

__device__ __forceinline__ float neg_inf() { return __int_as_float(0xff800000); }

__device__ __forceinline__ uint32_t smem_u32(const void* p) {
    uint32_t a;
    asm("{ .reg .u64 t; cvta.to.shared.u64 t, %1; cvt.u32.u64 %0, t; }" : "=r"(a) : "l"(p));
    return a;
}
__device__ __forceinline__ void split_bf16(float x, __nv_bfloat16& h, __nv_bfloat16& l) {
    h = __float2bfloat16(x);
    l = __float2bfloat16(x - __bfloat162float(h));
}

#define CP16(dst, src) asm volatile("cp.async.cg.shared.global [%0], [%1], 16;" :: "r"(dst), "l"(src))
#define CPCOMMIT() asm volatile("cp.async.commit_group;" ::: "memory")
#define CPWAIT0() asm volatile("cp.async.wait_group 0;" ::: "memory")

__device__ __forceinline__ void ldsm_x4(uint32_t* r, uint32_t addr) {
    asm volatile("ldmatrix.sync.aligned.m8n8.x4.shared.b16 {%0,%1,%2,%3}, [%4];"
        : "=r"(r[0]), "=r"(r[1]), "=r"(r[2]), "=r"(r[3]) : "r"(addr));
}
__device__ __forceinline__ void ldsm_x2(uint32_t* r, uint32_t addr) {
    asm volatile("ldmatrix.sync.aligned.m8n8.x2.shared.b16 {%0,%1}, [%2];"
        : "=r"(r[0]), "=r"(r[1]) : "r"(addr));
}
__device__ __forceinline__ void mma_bf16(float* c, const uint32_t* a, const uint32_t* b) {
    asm volatile(
        "mma.sync.aligned.m16n8k16.row.col.f32.bf16.bf16.f32 "
        "{%0,%1,%2,%3}, {%4,%5,%6,%7}, {%8,%9}, {%0,%1,%2,%3};"
        : "+f"(c[0]), "+f"(c[1]), "+f"(c[2]), "+f"(c[3])
        : "r"(a[0]), "r"(a[1]), "r"(a[2]), "r"(a[3]), "r"(b[0]), "r"(b[1]));
}

// One k16 step, mt-serial to minimize live registers.
// Stage layout: Ah@0, Al@10240, Bh@20480, Bl@30720 (bytes), pitch PCH halfs.
__device__ __forceinline__ void mma_tile_step2(uint32_t sb, int buf, int ks,
                                               int wm, int wn, int lane,
                                               float (*acc)[4][4])
{
    uint32_t base = sb + buf * BUFSZ;
    uint32_t bh[4][2], bl[4][2];
    int brow = lane & 7;
    int bcol = ks * 16 + ((lane >> 3) & 1) * 8;
#pragma unroll
    for (int nt = 0; nt < 4; nt++) {
        uint32_t ro = (uint32_t)(wn + nt * 8 + brow) * (PCH * 2) + bcol * 2;
        ldsm_x2(bh[nt], base + 20480 + ro);
        ldsm_x2(bl[nt], base + 30720 + ro);
    }
    int arow = lane & 15;
    int acol = ks * 16 + (lane >> 4) * 8;
#pragma unroll
    for (int mt = 0; mt < 4; mt++) {
        uint32_t ah[4], al[4];
        uint32_t ro = (uint32_t)(wm + mt * 16 + arow) * (PCH * 2) + acol * 2;
        ldsm_x4(ah, base + ro);
        ldsm_x4(al, base + 10240 + ro);
#pragma unroll
        for (int nt = 0; nt < 4; nt++) {
            mma_bf16(acc[mt][nt], ah, bh[nt]);
            mma_bf16(acc[mt][nt], ah, bl[nt]);
            mma_bf16(acc[mt][nt], al, bh[nt]);
        }
    }
}

// ============================================================
// K-1: split x into bf16 hi/lo
// ============================================================
__global__ __launch_bounds__(256) void splitx_kernel(const float* __restrict__ x)
{
    long idx = ((long)blockIdx.x * 256 + threadIdx.x) * 4;
    float4 a = *(const float4*)&x[idx];
    __nv_bfloat16 h0, h1, h2, h3, l0, l1, l2, l3;
    split_bf16(a.x, h0, l0);
    split_bf16(a.y, h1, l1);
    split_bf16(a.z, h2, l2);
    split_bf16(a.w, h3, l3);
    __nv_bfloat162 ph0, ph1, pl0, pl1;
    ph0.x = h0; ph0.y = h1; ph1.x = h2; ph1.y = h3;
    pl0.x = l0; pl0.y = l1; pl1.x = l2; pl1.y = l3;
    *(uint2*)&g_xh[idx] = make_uint2(*(uint32_t*)&ph0, *(uint32_t*)&ph1);
    *(uint2*)&g_xl[idx] = make_uint2(*(uint32_t*)&pl0, *(uint32_t*)&pl1);
}

// ============================================================
// K0: transpose + split W
// ============================================================
__global__ __launch_bounds__(256) void wt_kernel(const float* __restrict__ Wq,
                                                 const float* __restrict__ Wk,
                                                 const float* __restrict__ Wv)
{
    const float* W = (blockIdx.z == 0) ? Wq : ((blockIdx.z == 1) ? Wk : Wv);
    __shared__ float t[32][33];
    int tid = threadIdx.x;
    int tx = tid & 31, ty = tid >> 5;
    int k0 = blockIdx.x * 32, n0 = blockIdx.y * 32;
#pragma unroll
    for (int s = 0; s < 4; s++) t[ty + s * 8][tx] = W[(k0 + ty + s * 8) * D_E + n0 + tx];
    __syncthreads();
    long wb = (long)blockIdx.z * D_E * DIN;
#pragma unroll
    for (int s = 0; s < 4; s++) {
        int n = n0 + ty + s * 8, k = k0 + tx;
        __nv_bfloat16 h, l;
        split_bf16(t[tx][ty + s * 8], h, l);
        g_wth[wb + (long)n * DIN + k] = h;
        g_wtl[wb + (long)n * DIN + k] = l;
    }
}

// ============================================================
// K1: QKV via mma.sync, 2-stage, 1 sync/chunk, 2 CTAs/SM. grid (NT/128, 3)
// ============================================================
__global__ __launch_bounds__(256, 2) void qkv_mma_kernel()
{
    extern __shared__ char smc[];
    uint32_t sb = smem_u32(smc);
    int tid = threadIdx.x, lane = tid & 31, wid = tid >> 5;
    int w = blockIdx.y;
    long mBase = (long)blockIdx.x * 128;

    const __nv_bfloat16* sAh = g_xh + mBase * DIN;
    const __nv_bfloat16* sAl = g_xl + mBase * DIN;
    const __nv_bfloat16* sBh = g_wth + (long)w * D_E * DIN;
    const __nv_bfloat16* sBl = g_wtl + (long)w * D_E * DIN;

    int wm = (wid >> 2) * 64, wn = (wid & 3) * 32;
    float acc[4][4][4];
#pragma unroll
    for (int a = 0; a < 4; a++)
#pragma unroll
        for (int b = 0; b < 4; b++)
#pragma unroll
            for (int cc = 0; cc < 4; cc++) acc[a][b][cc] = 0.f;

#define QKV_LOAD(c, bf)                                                        \
    {                                                                          \
        int k0_ = (c) * 32;                                                    \
        uint32_t db_ = sb + (bf) * BUFSZ;                                      \
        for (int u = tid; u < 2048; u += 256) {                                \
            int arr = u >> 9, idx = u & 511, row = idx >> 2, seg = idx & 3;    \
            const __nv_bfloat16* s =                                           \
                (arr == 0) ? sAh : (arr == 1) ? sAl : (arr == 2) ? sBh : sBl;  \
            CP16(db_ + arr * 10240 + row * 80 + seg * 16,                      \
                 s + (long)row * DIN + k0_ + seg * 8);                         \
        }                                                                      \
        CPCOMMIT();                                                            \
    }

    QKV_LOAD(0, 0);
    for (int c = 0; c < 32; c++) {
        CPWAIT0();
        __syncthreads();
        if (c + 1 < 32) QKV_LOAD(c + 1, (c + 1) & 1);
        mma_tile_step2(sb, c & 1, 0, wm, wn, lane, acc);
        mma_tile_step2(sb, c & 1, 1, wm, wn, lane, acc);
    }
#undef QKV_LOAD
    __syncthreads();

    if (w < 2) {
        __nv_bfloat16* dh = w ? g_kh : g_qh;
        __nv_bfloat16* dl = w ? g_kl : g_ql;
#pragma unroll
        for (int mt = 0; mt < 4; mt++)
#pragma unroll
            for (int nt = 0; nt < 4; nt++) {
                int cc = wn + nt * 8 + (lane & 3) * 2;
#pragma unroll
                for (int h = 0; h < 2; h++) {
                    int row = wm + mt * 16 + (lane >> 2) + h * 8;
                    float v0 = acc[mt][nt][h * 2], v1 = acc[mt][nt][h * 2 + 1];
                    __nv_bfloat16 h0, h1, l0, l1;
                    split_bf16(v0, h0, l0);
                    split_bf16(v1, h1, l1);
                    __nv_bfloat162 ph, pl;
                    ph.x = h0; ph.y = h1; pl.x = l0; pl.y = l1;
                    long o = (mBase + row) * D_E + cc;
                    *(__nv_bfloat162*)&dh[o] = ph;
                    *(__nv_bfloat162*)&dl[o] = pl;
                }
            }
    } else {
        float* stage = (float*)smc;  // 128 x 129 f32 = 66048B < 2*BUFSZ
#pragma unroll
        for (int mt = 0; mt < 4; mt++)
#pragma unroll
            for (int nt = 0; nt < 4; nt++) {
                int cc = wn + nt * 8 + (lane & 3) * 2;
#pragma unroll
                for (int h = 0; h < 2; h++) {
                    int row = wm + mt * 16 + (lane >> 2) + h * 8;
                    stage[row * 129 + cc] = acc[mt][nt][h * 2];
                    stage[row * 129 + cc + 1] = acc[mt][nt][h * 2 + 1];
                }
            }
        __syncthreads();
        int nb = (int)(mBase >> 12);
        int tb = (int)(mBase & (T_S - 1));
        for (int u = tid; u < 8192; u += 256) {
            int d = u >> 6, tp = (u & 63) * 2;
            float v0 = stage[tp * 129 + d];
            float v1 = stage[(tp + 1) * 129 + d];
            __nv_bfloat16 h0, h1, l0, l1;
            split_bf16(v0, h0, l0);
            split_bf16(v1, h1, l1);
            __nv_bfloat162 ph, pl;
            ph.x = h0; ph.y = h1; pl.x = l0; pl.y = l1;
            long o = ((long)nb * D_E + d) * T_S + tb + tp;
            *(__nv_bfloat162*)&g_vth[o] = ph;
            *(__nv_bfloat162*)&g_vtl[o] = pl;
        }
    }
}

// ============================================================
// K2: scores S = Q K^T, 2-stage, 1 sync/chunk, fused partial stats.
// ============================================================
__global__ __launch_bounds__(256, 2) void scores_mma_kernel(float* __restrict__ att)
{
    int tri = blockIdx.x;
    int n = blockIdx.y;
    int i = (int)((sqrtf(8.f * tri + 1.f) - 1.f) * 0.5f);
    while ((i + 1) * (i + 2) / 2 <= tri) i++;
    while (i * (i + 1) / 2 > tri) i--;
    int j = tri - i * (i + 1) / 2;

    extern __shared__ char smc[];
    uint32_t sb = smem_u32(smc);
    int tid = threadIdx.x, lane = tid & 31, wid = tid >> 5;

    const __nv_bfloat16* sAh = g_qh + ((long)n * T_S + i * 128) * D_E;
    const __nv_bfloat16* sAl = g_ql + ((long)n * T_S + i * 128) * D_E;
    const __nv_bfloat16* sBh = g_kh + ((long)n * T_S + j * 128) * D_E;
    const __nv_bfloat16* sBl = g_kl + ((long)n * T_S + j * 128) * D_E;

    int wm = (wid >> 2) * 64, wn = (wid & 3) * 32;
    float acc[4][4][4];
#pragma unroll
    for (int a = 0; a < 4; a++)
#pragma unroll
        for (int b = 0; b < 4; b++)
#pragma unroll
            for (int cc = 0; cc < 4; cc++) acc[a][b][cc] = 0.f;

#define SC_LOAD(c, bf)                                                         \
    {                                                                          \
        int k0_ = (c) * 32;                                                    \
        uint32_t db_ = sb + (bf) * BUFSZ;                                      \
        for (int u = tid; u < 2048; u += 256) {                                \
            int arr = u >> 9, idx = u & 511, row = idx >> 2, seg = idx & 3;    \
            const __nv_bfloat16* s =                                           \
                (arr == 0) ? sAh : (arr == 1) ? sAl : (arr == 2) ? sBh : sBl;  \
            CP16(db_ + arr * 10240 + row * 80 + seg * 16,                      \
                 s + (long)row * D_E + k0_ + seg * 8);                         \
        }                                                                      \
        CPCOMMIT();                                                            \
    }

    SC_LOAD(0, 0);
    for (int c = 0; c < 4; c++) {
        CPWAIT0();
        __syncthreads();
        if (c + 1 < 4) SC_LOAD(c + 1, (c + 1) & 1);
        mma_tile_step2(sb, c & 1, 0, wm, wn, lane, acc);
        mma_tile_step2(sb, c & 1, 1, wm, wn, lane, acc);
    }
#undef SC_LOAD

    // ---- epilogue: att write + fused partial softmax stats (two-pass)
    float* pm = (float*)(smc + 2 * BUFSZ);  // [128][4] = 2048B
    float* ps = pm + 512;                   // [128][4] = 2048B
    float* attn = att + (long)n * T_S * T_S;
    float NI = neg_inf();

    __syncthreads();
#pragma unroll
    for (int mt = 0; mt < 4; mt++)
#pragma unroll
        for (int h = 0; h < 2; h++) {
            int row = wm + mt * 16 + (lane >> 2) + h * 8;
            int tg = i * 128 + row;
            float m = NI;
#pragma unroll
            for (int nt = 0; nt < 4; nt++)
#pragma unroll
                for (int e = 0; e < 2; e++) {
                    int s = j * 128 + wn + nt * 8 + (lane & 3) * 2 + e;
                    if (s <= tg) {
                        float v = acc[mt][nt][h * 2 + e];
                        float ev = (v == 0.0f) ? NI : v;
                        attn[(long)tg * T_S + s] = ev;
                        m = fmaxf(m, ev);
                    }
                }
            m = fmaxf(m, __shfl_xor_sync(0xffffffffu, m, 1));
            m = fmaxf(m, __shfl_xor_sync(0xffffffffu, m, 2));
            float ssum = 0.f;
            if (m != NI) {
#pragma unroll
                for (int nt = 0; nt < 4; nt++)
#pragma unroll
                    for (int e = 0; e < 2; e++) {
                        int s = j * 128 + wn + nt * 8 + (lane & 3) * 2 + e;
                        if (s <= tg) {
                            float v = acc[mt][nt][h * 2 + e];
                            float ev = (v == 0.0f) ? NI : v;
                            ssum += __expf(ev - m);
                        }
                    }
            }
            ssum += __shfl_xor_sync(0xffffffffu, ssum, 1);
            ssum += __shfl_xor_sync(0xffffffffu, ssum, 2);
            if ((lane & 3) == 0) {
                pm[row * 4 + (wid & 3)] = m;
                ps[row * 4 + (wid & 3)] = ssum;
            }
        }
    __syncthreads();

    if (tid < 128) {
        float m0 = pm[tid * 4], m1 = pm[tid * 4 + 1], m2 = pm[tid * 4 + 2], m3 = pm[tid * 4 + 3];
        float M = fmaxf(fmaxf(m0, m1), fmaxf(m2, m3));
        float S = 0.f;
        if (M != NI) {
            S = ps[tid * 4] * __expf(m0 - M) + ps[tid * 4 + 1] * __expf(m1 - M) +
                ps[tid * 4 + 2] * __expf(m2 - M) + ps[tid * 4 + 3] * __expf(m3 - M);
        }
        long o = ((long)n * T_S + i * 128 + tid) * 32 + j;
        g_pmax[o] = M;
        g_psum[o] = S;
    }
}

// ============================================================
// K3: combine partial stats -> g_rowmax/g_rowsum. One warp per row.
// ============================================================
__global__ void combine_kernel()
{
    int w = (blockIdx.x * blockDim.x + threadIdx.x) >> 5;
    int lane = threadIdx.x & 31;
    if (w >= NT) return;
    int t = w & (T_S - 1);
    int jmax = t >> 7;
    float NI = neg_inf();
    float m = NI, s = 0.f;
    if (lane <= jmax) {
        m = g_pmax[(long)w * 32 + lane];
        s = g_psum[(long)w * 32 + lane];
    }
    float M = m;
#pragma unroll
    for (int o = 16; o; o >>= 1) M = fmaxf(M, __shfl_xor_sync(0xffffffffu, M, o));
    float v = (m == NI) ? 0.f : s * __expf(m - M);
#pragma unroll
    for (int o = 16; o; o >>= 1) v += __shfl_xor_sync(0xffffffffu, v, o);
    if (lane == 0) {
        g_rowmax[w] = M;
        g_rowsum[w] = v;
    }
}

// ============================================================
// K4: split-K PV, 2-stage, 1 sync/chunk. grid (80, N_B).
// ============================================================
__global__ __launch_bounds__(256, 2) void pv_mma_kernel(float* __restrict__ att,
                                                        float* __restrict__ out)
{
    int b = blockIdx.x;
    int n = blockIdx.y;
    int i = 31, jg = 0;
    for (i = 31; i >= 0; --i) {
        int g = (i + 8) >> 3;
        if (b < g) { jg = b; break; }
        b -= g;
    }
    int ngroups = (i + 8) >> 3;
    int kStart = jg << 10;
    int kEndA = min((jg + 1) << 10, (i + 1) << 7);
    int nc = (kEndA - kStart) >> 5;

    extern __shared__ char smc[];
    uint32_t sb = smem_u32(smc);
    float* smax = (float*)(smc + 2 * BUFSZ);  // 512B
    float* sinv = smax + 128;                 // 512B
    int tid = threadIdx.x, lane = tid & 31, wid = tid >> 5;

    float* attn = att + (long)n * T_S * T_S;

    if (tid < 128) {
        int r = n * T_S + (i << 7) + tid;
        smax[tid] = g_rowmax[r];
        sinv[tid] = 1.f / g_rowsum[r];
    }
    __syncthreads();

    int wm = (wid >> 2) * 64, wn = (wid & 3) * 32;
    float acc[4][4][4];
#pragma unroll
    for (int a = 0; a < 4; a++)
#pragma unroll
        for (int b2 = 0; b2 < 4; b2++)
#pragma unroll
            for (int cc = 0; cc < 4; cc++) acc[a][b2][cc] = 0.f;

#define PV_LDB(c, bf)                                                          \
    {                                                                          \
        int k0_ = kStart + (c) * 32;                                           \
        uint32_t db_ = sb + (bf) * BUFSZ + 20480;                              \
        for (int u = tid; u < 1024; u += 256) {                                \
            int arr = u >> 9, idx = u & 511, row = idx >> 2, seg = idx & 3;    \
            const __nv_bfloat16* s = (arr ? g_vtl : g_vth) +                   \
                ((long)n * D_E + row) * T_S + k0_ + seg * 8;                   \
            CP16(db_ + arr * 10240 + row * 80 + seg * 16, s);                  \
        }                                                                      \
        CPCOMMIT();                                                            \
    }

#define PV_LDA(c, ar)                                                          \
    {                                                                          \
        int k0_ = kStart + (c) * 32;                                           \
        _Pragma("unroll") for (int q = 0; q < 4; q++) {                        \
            int idx = tid + q * 256;                                           \
            int row = idx >> 3, seg = idx & 7;                                 \
            ar[q] = *(const float4*)&attn[(long)((i << 7) + row) * T_S + k0_ + seg * 4]; \
        }                                                                      \
    }

#define PV_PROC(c, ar, bf)                                                     \
    {                                                                          \
        int k0_ = kStart + (c) * 32;                                           \
        _Pragma("unroll") for (int q = 0; q < 4; q++) {                        \
            int idx = tid + q * 256;                                           \
            int row = idx >> 3, seg = idx & 7;                                 \
            int t = (i << 7) + row;                                            \
            int s0 = k0_ + seg * 4;                                            \
            float rm = smax[row], ri = sinv[row];                              \
            float p0 = (s0 + 0 <= t) ? __expf(ar[q].x - rm) * ri : 0.f;        \
            float p1 = (s0 + 1 <= t) ? __expf(ar[q].y - rm) * ri : 0.f;        \
            float p2 = (s0 + 2 <= t) ? __expf(ar[q].z - rm) * ri : 0.f;        \
            float p3 = (s0 + 3 <= t) ? __expf(ar[q].w - rm) * ri : 0.f;        \
            *(float4*)&attn[(long)t * T_S + s0] = make_float4(p0, p1, p2, p3); \
            __nv_bfloat16 h0, h1, h2, h3, l0, l1, l2, l3;                      \
            split_bf16(p0, h0, l0); split_bf16(p1, h1, l1);                    \
            split_bf16(p2, h2, l2); split_bf16(p3, h3, l3);                    \
            __nv_bfloat162 ph0, ph1, pl0, pl1;                                 \
            ph0.x = h0; ph0.y = h1; ph1.x = h2; ph1.y = h3;                    \
            pl0.x = l0; pl0.y = l1; pl1.x = l2; pl1.y = l3;                    \
            uint32_t so = row * 80 + seg * 8;                                  \
            *(uint2*)(smc + (bf) * BUFSZ + so) =                               \
                make_uint2(*(uint32_t*)&ph0, *(uint32_t*)&ph1);                \
            *(uint2*)(smc + (bf) * BUFSZ + 10240 + so) =                       \
                make_uint2(*(uint32_t*)&pl0, *(uint32_t*)&pl1);                \
        }                                                                      \
    }

    float4 ar[4];
    PV_LDB(0, 0);
    PV_LDA(0, ar);
    PV_PROC(0, ar, 0);

    for (int c = 0; c < nc; c++) {
        CPWAIT0();
        __syncthreads();
        if (c + 1 < nc) {
            PV_LDB(c + 1, (c + 1) & 1);
            PV_LDA(c + 1, ar);
        }
        mma_tile_step2(sb, c & 1, 0, wm, wn, lane, acc);
        mma_tile_step2(sb, c & 1, 1, wm, wn, lane, acc);
        if (c + 1 < nc) PV_PROC(c + 1, ar, (c + 1) & 1);
    }
#undef PV_LDB
#undef PV_LDA
#undef PV_PROC

    float* dst;
    if (ngroups == 1) dst = out + ((long)n * T_S + (i << 7)) * D_E;
    else dst = g_part + (((long)(n * 24 + (i - 8)) * 4 + jg) << 14);
#pragma unroll
    for (int mt = 0; mt < 4; mt++)
#pragma unroll
        for (int nt = 0; nt < 4; nt++) {
            int cc = wn + nt * 8 + (lane & 3) * 2;
#pragma unroll
            for (int h = 0; h < 2; h++) {
                int row = wm + mt * 16 + (lane >> 2) + h * 8;
                *(float2*)&dst[(long)row * 128 + cc] =
                    make_float2(acc[mt][nt][h * 2], acc[mt][nt][h * 2 + 1]);
            }
        }

    // zero-fill att above band (last group), div-free
    if (jg == ngroups - 1) {
        int zstart = (i + 1) << 7;
        if (zstart < T_S) {
            float4 z = make_float4(0.f, 0.f, 0.f, 0.f);
            for (int row = wid; row < 128; row += 8) {
                float* rp = attn + (long)((i << 7) + row) * T_S;
                for (int cc = zstart + lane * 4; cc < T_S; cc += 128)
                    *(float4*)&rp[cc] = z;
            }
        }
    }
}

// ============================================================
// K5: reduce split-K partials
// ============================================================
__global__ void reduce_kernel(float* __restrict__ out)
{
    int ii = blockIdx.x;
    int n = blockIdx.y;
    int i = ii + 8;
    int ng = (i + 8) >> 3;
    const float* base = g_part + (((long)(n * 24 + ii) * 4) << 14);
    float* o = out + ((long)n * T_S + (i << 7)) * D_E;
    for (int e = threadIdx.x * 4; e < 128 * 128; e += 1024) {
        float4 s = *(const float4*)&base[e];
        for (int g = 1; g < ng; g++) {
            float4 p = *(const float4*)&base[((long)g << 14) + e];
            s.x += p.x; s.y += p.y; s.z += p.z; s.w += p.w;
        }
        *(float4*)&o[e] = s;
    }
}

// ============================================================
extern "C" void kernel_launch(void* const* d_in, const int* in_sizes, int n_in,
                              void* d_out, int out_size)
{
    const float* x  = (const float*)d_in[0];
    const float* Wq = (const float*)d_in[1];
    const float* Wk = (const float*)d_in[2];
    const float* Wv = (const float*)d_in[3];

    const long NTD = (long)NT * D_E;
    const long NTT = (long)N_B * T_S * T_S;

    float* dout = (float*)d_out;
    float* out_ptr;
    float* att_ptr;
    if ((long)out_size >= NTD + NTT) {
        out_ptr = dout;
        att_ptr = dout + NTD;
    } else if ((long)out_size == NTT) {
        att_ptr = dout;
        void* fb = nullptr;
        cudaGetSymbolAddress(&fb, g_out_fallback);
        out_ptr = (float*)fb;
    } else {
        out_ptr = dout;
        att_ptr = dout;
    }

    cudaFuncSetAttribute(qkv_mma_kernel, cudaFuncAttributeMaxDynamicSharedMemorySize, 2 * BUFSZ);
    cudaFuncSetAttribute(scores_mma_kernel, cudaFuncAttributeMaxDynamicSharedMemorySize, 2 * BUFSZ + 4096);
    cudaFuncSetAttribute(pv_mma_kernel, cudaFuncAttributeMaxDynamicSharedMemorySize, 2 * BUFSZ + 1024);

    splitx_kernel<<<(long)NT * DIN / 1024, 256>>>(x);
    wt_kernel<<<dim3(DIN / 32, D_E / 32, 3), 256>>>(Wq, Wk, Wv);

    qkv_mma_kernel<<<dim3(NT / 128, 3), 256, 2 * BUFSZ>>>();

    int nTiles = T_S / 128;
    int nTri = nTiles * (nTiles + 1) / 2;
    scores_mma_kernel<<<dim3(nTri, N_B), 256, 2 * BUFSZ + 4096>>>(att_ptr);

    combine_kernel<<<NT / 8, 256>>>();

    pv_mma_kernel<<<dim3(80, N_B), 256, 2 * BUFSZ + 1024>>>(att_ptr, out_ptr);

    reduce_kernel<<<dim3(24, N_B), 256>>>(out_ptr);
}

// round 9
// speedup vs baseline: 3.7006x; 1.0593x over previous
#include <cuda_runtime.h>
#include <cuda_bf16.h>
#include <math.h>
#include <stdint.h>

#define N_B 4
#define T_S 4096
#define DIN 1024
#define D_E 128
#define NT (N_B * T_S)
#define PCH 40      // smem row pitch in halfs (32 + 8 pad)
#define BUFSZ 40960 // one stage: 4 regions x 10240B

// ---- scratch (device globals: allocation-free) ----
__device__ __nv_bfloat16 g_xh[(long)NT * DIN];
__device__ __nv_bfloat16 g_xl[(long)NT * DIN];
__device__ __nv_bfloat16 g_wth[3 * D_E * DIN];
__device__ __nv_bfloat16 g_wtl[3 * D_E * DIN];
__device__ __nv_bfloat16 g_qh[NT * D_E];
__device__ __nv_bfloat16 g_ql[NT * D_E];
__device__ __nv_bfloat16 g_kh[NT * D_E];
__device__ __nv_bfloat16 g_kl[NT * D_E];
__device__ __nv_bfloat16 g_vth[(long)N_B * D_E * T_S];
__device__ __nv_bfloat16 g_vtl[(long)N_B * D_E * T_S];
__device__ float g_pmax[(long)NT * 32];
__device__ float g_psum[(long)NT * 32];
__device__ float g_part[(long)4 * 24 * 4 * 128 * 128];
__device__ float g_out_fallback[NT * D_E];

__device__ __forceinline__ float neg_inf() { return __int_as_float(0xff800000); }

__device__ __forceinline__ uint32_t smem_u32(const void* p) {
    uint32_t a;
    asm("{ .reg .u64 t; cvta.to.shared.u64 t, %1; cvt.u32.u64 %0, t; }" : "=r"(a) : "l"(p));
    return a;
}
__device__ __forceinline__ void split_bf16(float x, __nv_bfloat16& h, __nv_bfloat16& l) {
    h = __float2bfloat16(x);
    l = __float2bfloat16(x - __bfloat162float(h));
}

#define CP16(dst, src) asm volatile("cp.async.cg.shared.global [%0], [%1], 16;" :: "r"(dst), "l"(src))
#define CPCOMMIT() asm volatile("cp.async.commit_group;" ::: "memory")
#define CPWAIT0() asm volatile("cp.async.wait_group 0;" ::: "memory")

__device__ __forceinline__ void ldsm_x4(uint32_t* r, uint32_t addr) {
    asm volatile("ldmatrix.sync.aligned.m8n8.x4.shared.b16 {%0,%1,%2,%3}, [%4];"
        : "=r"(r[0]), "=r"(r[1]), "=r"(r[2]), "=r"(r[3]) : "r"(addr));
}
__device__ __forceinline__ void ldsm_x2(uint32_t* r, uint32_t addr) {
    asm volatile("ldmatrix.sync.aligned.m8n8.x2.shared.b16 {%0,%1}, [%2];"
        : "=r"(r[0]), "=r"(r[1]) : "r"(addr));
}
__device__ __forceinline__ void mma_bf16(float* c, const uint32_t* a, const uint32_t* b) {
    asm volatile(
        "mma.sync.aligned.m16n8k16.row.col.f32.bf16.bf16.f32 "
        "{%0,%1,%2,%3}, {%4,%5,%6,%7}, {%8,%9}, {%0,%1,%2,%3};"
        : "+f"(c[0]), "+f"(c[1]), "+f"(c[2]), "+f"(c[3])
        : "r"(a[0]), "r"(a[1]), "r"(a[2]), "r"(a[3]), "r"(b[0]), "r"(b[1]));
}

// One k16 step, mt-serial, hoisted per-warp addresses.
// Region layout within a stage: Ah@0, Al@10240, Bh@20480, Bl@30720.
// aoff/boff are lane-dependent byte offsets computed once per kernel.
__device__ __forceinline__ void mma_tile_step2(uint32_t base, int ks,
                                               uint32_t aoff, uint32_t boff,
                                               float (*acc)[4][4])
{
    uint32_t ko = (uint32_t)ks * 32;
    uint32_t bh[4][2], bl[4][2];
#pragma unroll
    for (int nt = 0; nt < 4; nt++) {
        uint32_t ro = boff + nt * (8 * 80) + ko;
        ldsm_x2(bh[nt], base + 20480 + ro);
        ldsm_x2(bl[nt], base + 30720 + ro);
    }
#pragma unroll
    for (int mt = 0; mt < 4; mt++) {
        uint32_t ah[4], al[4];
        uint32_t ro = aoff + mt * (16 * 80) + ko;
        ldsm_x4(ah, base + ro);
        ldsm_x4(al, base + 10240 + ro);
#pragma unroll
        for (int nt = 0; nt < 4; nt++) {
            mma_bf16(acc[mt][nt], ah, bh[nt]);
            mma_bf16(acc[mt][nt], ah, bl[nt]);
            mma_bf16(acc[mt][nt], al, bh[nt]);
        }
    }
}

// ============================================================
// K-1: split x into bf16 hi/lo
// ============================================================
__global__ __launch_bounds__(256) void splitx_kernel(const float* __restrict__ x)
{
    long idx = ((long)blockIdx.x * 256 + threadIdx.x) * 4;
    float4 a = *(const float4*)&x[idx];
    __nv_bfloat16 h0, h1, h2, h3, l0, l1, l2, l3;
    split_bf16(a.x, h0, l0);
    split_bf16(a.y, h1, l1);
    split_bf16(a.z, h2, l2);
    split_bf16(a.w, h3, l3);
    __nv_bfloat162 ph0, ph1, pl0, pl1;
    ph0.x = h0; ph0.y = h1; ph1.x = h2; ph1.y = h3;
    pl0.x = l0; pl0.y = l1; pl1.x = l2; pl1.y = l3;
    *(uint2*)&g_xh[idx] = make_uint2(*(uint32_t*)&ph0, *(uint32_t*)&ph1);
    *(uint2*)&g_xl[idx] = make_uint2(*(uint32_t*)&pl0, *(uint32_t*)&pl1);
}

// ============================================================
// K0: transpose + split W
// ============================================================
__global__ __launch_bounds__(256) void wt_kernel(const float* __restrict__ Wq,
                                                 const float* __restrict__ Wk,
                                                 const float* __restrict__ Wv)
{
    const float* W = (blockIdx.z == 0) ? Wq : ((blockIdx.z == 1) ? Wk : Wv);
    __shared__ float t[32][33];
    int tid = threadIdx.x;
    int tx = tid & 31, ty = tid >> 5;
    int k0 = blockIdx.x * 32, n0 = blockIdx.y * 32;
#pragma unroll
    for (int s = 0; s < 4; s++) t[ty + s * 8][tx] = W[(k0 + ty + s * 8) * D_E + n0 + tx];
    __syncthreads();
    long wb = (long)blockIdx.z * D_E * DIN;
#pragma unroll
    for (int s = 0; s < 4; s++) {
        int n = n0 + ty + s * 8, k = k0 + tx;
        __nv_bfloat16 h, l;
        split_bf16(t[tx][ty + s * 8], h, l);
        g_wth[wb + (long)n * DIN + k] = h;
        g_wtl[wb + (long)n * DIN + k] = l;
    }
}

// ============================================================
// K1: QKV via mma.sync, 2-stage, 1 sync/chunk, 2 CTAs/SM. grid (NT/128, 3)
// ============================================================
__global__ __launch_bounds__(256, 2) void qkv_mma_kernel()
{
    extern __shared__ char smc[];
    uint32_t sb = smem_u32(smc);
    int tid = threadIdx.x, lane = tid & 31, wid = tid >> 5;
    int w = blockIdx.y;
    long mBase = (long)blockIdx.x * 128;

    const __nv_bfloat16* sAh = g_xh + mBase * DIN;
    const __nv_bfloat16* sAl = g_xl + mBase * DIN;
    const __nv_bfloat16* sBh = g_wth + (long)w * D_E * DIN;
    const __nv_bfloat16* sBl = g_wtl + (long)w * D_E * DIN;

    int wm = (wid >> 2) * 64, wn = (wid & 3) * 32;
    uint32_t aoff = (uint32_t)(wm + (lane & 15)) * 80 + (lane >> 4) * 16;
    uint32_t boff = (uint32_t)(wn + (lane & 7)) * 80 + ((lane >> 3) & 1) * 16;

    float acc[4][4][4];
#pragma unroll
    for (int a = 0; a < 4; a++)
#pragma unroll
        for (int b = 0; b < 4; b++)
#pragma unroll
            for (int cc = 0; cc < 4; cc++) acc[a][b][cc] = 0.f;

#define QKV_LOAD(c, bf)                                                        \
    {                                                                          \
        int k0_ = (c) * 32;                                                    \
        uint32_t db_ = sb + (bf) * BUFSZ;                                      \
        for (int u = tid; u < 2048; u += 256) {                                \
            int arr = u >> 9, idx = u & 511, row = idx >> 2, seg = idx & 3;    \
            const __nv_bfloat16* s =                                           \
                (arr == 0) ? sAh : (arr == 1) ? sAl : (arr == 2) ? sBh : sBl;  \
            CP16(db_ + arr * 10240 + row * 80 + seg * 16,                      \
                 s + (long)row * DIN + k0_ + seg * 8);                         \
        }                                                                      \
        CPCOMMIT();                                                            \
    }

    QKV_LOAD(0, 0);
    for (int c = 0; c < 32; c++) {
        CPWAIT0();
        __syncthreads();
        if (c + 1 < 32) QKV_LOAD(c + 1, (c + 1) & 1);
        uint32_t base = sb + (c & 1) * BUFSZ;
        mma_tile_step2(base, 0, aoff, boff, acc);
        mma_tile_step2(base, 1, aoff, boff, acc);
    }
#undef QKV_LOAD
    __syncthreads();

    if (w < 2) {
        __nv_bfloat16* dh = w ? g_kh : g_qh;
        __nv_bfloat16* dl = w ? g_kl : g_ql;
#pragma unroll
        for (int mt = 0; mt < 4; mt++)
#pragma unroll
            for (int nt = 0; nt < 4; nt++) {
                int cc = wn + nt * 8 + (lane & 3) * 2;
#pragma unroll
                for (int h = 0; h < 2; h++) {
                    int row = wm + mt * 16 + (lane >> 2) + h * 8;
                    float v0 = acc[mt][nt][h * 2], v1 = acc[mt][nt][h * 2 + 1];
                    __nv_bfloat16 h0, h1, l0, l1;
                    split_bf16(v0, h0, l0);
                    split_bf16(v1, h1, l1);
                    __nv_bfloat162 ph, pl;
                    ph.x = h0; ph.y = h1; pl.x = l0; pl.y = l1;
                    long o = (mBase + row) * D_E + cc;
                    *(__nv_bfloat162*)&dh[o] = ph;
                    *(__nv_bfloat162*)&dl[o] = pl;
                }
            }
    } else {
        float* stage = (float*)smc;  // 128 x 129 f32 = 66048B < 2*BUFSZ
#pragma unroll
        for (int mt = 0; mt < 4; mt++)
#pragma unroll
            for (int nt = 0; nt < 4; nt++) {
                int cc = wn + nt * 8 + (lane & 3) * 2;
#pragma unroll
                for (int h = 0; h < 2; h++) {
                    int row = wm + mt * 16 + (lane >> 2) + h * 8;
                    stage[row * 129 + cc] = acc[mt][nt][h * 2];
                    stage[row * 129 + cc + 1] = acc[mt][nt][h * 2 + 1];
                }
            }
        __syncthreads();
        int nb = (int)(mBase >> 12);
        int tb = (int)(mBase & (T_S - 1));
        for (int u = tid; u < 8192; u += 256) {
            int d = u >> 6, tp = (u & 63) * 2;
            float v0 = stage[tp * 129 + d];
            float v1 = stage[(tp + 1) * 129 + d];
            __nv_bfloat16 h0, h1, l0, l1;
            split_bf16(v0, h0, l0);
            split_bf16(v1, h1, l1);
            __nv_bfloat162 ph, pl;
            ph.x = h0; ph.y = h1; pl.x = l0; pl.y = l1;
            long o = ((long)nb * D_E + d) * T_S + tb + tp;
            *(__nv_bfloat162*)&g_vth[o] = ph;
            *(__nv_bfloat162*)&g_vtl[o] = pl;
        }
    }
}

// ============================================================
// K2: scores. Full 32x32 tile grid: j>i tiles just zero-fill att.
// j<=i tiles: S = Q K^T + fused partial softmax stats.
// ============================================================
__global__ __launch_bounds__(256, 2) void scores_mma_kernel(float* __restrict__ att)
{
    int i = blockIdx.x >> 5;
    int j = blockIdx.x & 31;
    int n = blockIdx.y;
    float* attn = att + (long)n * T_S * T_S;

    int tid = threadIdx.x;

    if (j > i) {
        // pure zero-fill tile (upper triangle)
        float4 z = make_float4(0.f, 0.f, 0.f, 0.f);
        float* tp = attn + (long)(i * 128) * T_S + j * 128;
#pragma unroll 4
        for (int u = tid; u < 4096; u += 256) {
            int row = u >> 5, c4 = u & 31;
            *(float4*)&tp[(long)row * T_S + c4 * 4] = z;
        }
        return;
    }

    extern __shared__ char smc[];
    uint32_t sb = smem_u32(smc);
    int lane = tid & 31, wid = tid >> 5;

    const __nv_bfloat16* sAh = g_qh + ((long)n * T_S + i * 128) * D_E;
    const __nv_bfloat16* sAl = g_ql + ((long)n * T_S + i * 128) * D_E;
    const __nv_bfloat16* sBh = g_kh + ((long)n * T_S + j * 128) * D_E;
    const __nv_bfloat16* sBl = g_kl + ((long)n * T_S + j * 128) * D_E;

    int wm = (wid >> 2) * 64, wn = (wid & 3) * 32;
    uint32_t aoff = (uint32_t)(wm + (lane & 15)) * 80 + (lane >> 4) * 16;
    uint32_t boff = (uint32_t)(wn + (lane & 7)) * 80 + ((lane >> 3) & 1) * 16;

    float acc[4][4][4];
#pragma unroll
    for (int a = 0; a < 4; a++)
#pragma unroll
        for (int b = 0; b < 4; b++)
#pragma unroll
            for (int cc = 0; cc < 4; cc++) acc[a][b][cc] = 0.f;

#define SC_LOAD(c, bf)                                                         \
    {                                                                          \
        int k0_ = (c) * 32;                                                    \
        uint32_t db_ = sb + (bf) * BUFSZ;                                      \
        for (int u = tid; u < 2048; u += 256) {                                \
            int arr = u >> 9, idx = u & 511, row = idx >> 2, seg = idx & 3;    \
            const __nv_bfloat16* s =                                           \
                (arr == 0) ? sAh : (arr == 1) ? sAl : (arr == 2) ? sBh : sBl;  \
            CP16(db_ + arr * 10240 + row * 80 + seg * 16,                      \
                 s + (long)row * D_E + k0_ + seg * 8);                         \
        }                                                                      \
        CPCOMMIT();                                                            \
    }

    SC_LOAD(0, 0);
    for (int c = 0; c < 4; c++) {
        CPWAIT0();
        __syncthreads();
        if (c + 1 < 4) SC_LOAD(c + 1, (c + 1) & 1);
        uint32_t base = sb + (c & 1) * BUFSZ;
        mma_tile_step2(base, 0, aoff, boff, acc);
        mma_tile_step2(base, 1, aoff, boff, acc);
    }
#undef SC_LOAD

    // ---- epilogue: att write + fused partial softmax stats (two-pass)
    float* pm = (float*)(smc + 2 * BUFSZ);  // [128][4]
    float* ps = pm + 512;                   // [128][4]
    float NI = neg_inf();

    __syncthreads();
#pragma unroll
    for (int mt = 0; mt < 4; mt++)
#pragma unroll
        for (int h = 0; h < 2; h++) {
            int row = wm + mt * 16 + (lane >> 2) + h * 8;
            int tg = i * 128 + row;
            float m = NI;
#pragma unroll
            for (int nt = 0; nt < 4; nt++)
#pragma unroll
                for (int e = 0; e < 2; e++) {
                    int s = j * 128 + wn + nt * 8 + (lane & 3) * 2 + e;
                    if (s <= tg) {
                        float v = acc[mt][nt][h * 2 + e];
                        float ev = (v == 0.0f) ? NI : v;
                        attn[(long)tg * T_S + s] = ev;
                        m = fmaxf(m, ev);
                    }
                }
            m = fmaxf(m, __shfl_xor_sync(0xffffffffu, m, 1));
            m = fmaxf(m, __shfl_xor_sync(0xffffffffu, m, 2));
            float ssum = 0.f;
            if (m != NI) {
#pragma unroll
                for (int nt = 0; nt < 4; nt++)
#pragma unroll
                    for (int e = 0; e < 2; e++) {
                        int s = j * 128 + wn + nt * 8 + (lane & 3) * 2 + e;
                        if (s <= tg) {
                            float v = acc[mt][nt][h * 2 + e];
                            float ev = (v == 0.0f) ? NI : v;
                            ssum += __expf(ev - m);
                        }
                    }
            }
            ssum += __shfl_xor_sync(0xffffffffu, ssum, 1);
            ssum += __shfl_xor_sync(0xffffffffu, ssum, 2);
            if ((lane & 3) == 0) {
                pm[row * 4 + (wid & 3)] = m;
                ps[row * 4 + (wid & 3)] = ssum;
            }
        }
    __syncthreads();

    if (tid < 128) {
        float m0 = pm[tid * 4], m1 = pm[tid * 4 + 1], m2 = pm[tid * 4 + 2], m3 = pm[tid * 4 + 3];
        float M = fmaxf(fmaxf(m0, m1), fmaxf(m2, m3));
        float S = 0.f;
        if (M != NI) {
            S = ps[tid * 4] * __expf(m0 - M) + ps[tid * 4 + 1] * __expf(m1 - M) +
                ps[tid * 4 + 2] * __expf(m2 - M) + ps[tid * 4 + 3] * __expf(m3 - M);
        }
        long o = ((long)n * T_S + i * 128 + tid) * 32 + j;
        g_pmax[o] = M;
        g_psum[o] = S;
    }
}

// ============================================================
// K4: split-K PV, 2-stage, 1 sync/chunk, inline stats combine.
// grid (80, N_B).
// ============================================================
__global__ __launch_bounds__(256, 2) void pv_mma_kernel(float* __restrict__ att,
                                                        float* __restrict__ out)
{
    int b = blockIdx.x;
    int n = blockIdx.y;
    int i = 31, jg = 0;
    for (i = 31; i >= 0; --i) {
        int g = (i + 8) >> 3;
        if (b < g) { jg = b; break; }
        b -= g;
    }
    int ngroups = (i + 8) >> 3;
    int kStart = jg << 10;
    int kEndA = min((jg + 1) << 10, (i + 1) << 7);
    int nc = (kEndA - kStart) >> 5;

    extern __shared__ char smc[];
    uint32_t sb = smem_u32(smc);
    float* smax = (float*)(smc + 2 * BUFSZ);  // 512B
    float* sinv = smax + 128;                 // 512B
    int tid = threadIdx.x, lane = tid & 31, wid = tid >> 5;

    float* attn = att + (long)n * T_S * T_S;

    // inline combine of per-tile softmax partials
    if (tid < 128) {
        long r = (long)n * T_S + (i << 7) + tid;
        const float* pmr = g_pmax + r * 32;
        const float* psr = g_psum + r * 32;
        float NI = neg_inf();
        float M = NI;
        for (int jj = 0; jj <= i; jj++) M = fmaxf(M, pmr[jj]);
        float S = 0.f;
        for (int jj = 0; jj <= i; jj++) {
            float mj = pmr[jj];
            if (mj != NI) S += psr[jj] * __expf(mj - M);
        }
        smax[tid] = M;
        sinv[tid] = 1.f / S;
    }
    __syncthreads();

    int wm = (wid >> 2) * 64, wn = (wid & 3) * 32;
    uint32_t aoff = (uint32_t)(wm + (lane & 15)) * 80 + (lane >> 4) * 16;
    uint32_t boff = (uint32_t)(wn + (lane & 7)) * 80 + ((lane >> 3) & 1) * 16;

    float acc[4][4][4];
#pragma unroll
    for (int a = 0; a < 4; a++)
#pragma unroll
        for (int b2 = 0; b2 < 4; b2++)
#pragma unroll
            for (int cc = 0; cc < 4; cc++) acc[a][b2][cc] = 0.f;

#define PV_LDB(c, bf)                                                          \
    {                                                                          \
        int k0_ = kStart + (c) * 32;                                           \
        uint32_t db_ = sb + (bf) * BUFSZ + 20480;                              \
        for (int u = tid; u < 1024; u += 256) {                                \
            int arr = u >> 9, idx = u & 511, row = idx >> 2, seg = idx & 3;    \
            const __nv_bfloat16* s = (arr ? g_vtl : g_vth) +                   \
                ((long)n * D_E + row) * T_S + k0_ + seg * 8;                   \
            CP16(db_ + arr * 10240 + row * 80 + seg * 16, s);                  \
        }                                                                      \
        CPCOMMIT();                                                            \
    }

#define PV_LDA(c, ar)                                                          \
    {                                                                          \
        int k0_ = kStart + (c) * 32;                                           \
        _Pragma("unroll") for (int q = 0; q < 4; q++) {                        \
            int idx = tid + q * 256;                                           \
            int row = idx >> 3, seg = idx & 7;                                 \
            ar[q] = *(const float4*)&attn[(long)((i << 7) + row) * T_S + k0_ + seg * 4]; \
        }                                                                      \
    }

#define PV_PROC(c, ar, bf)                                                     \
    {                                                                          \
        int k0_ = kStart + (c) * 32;                                           \
        _Pragma("unroll") for (int q = 0; q < 4; q++) {                        \
            int idx = tid + q * 256;                                           \
            int row = idx >> 3, seg = idx & 7;                                 \
            int t = (i << 7) + row;                                            \
            int s0 = k0_ + seg * 4;                                            \
            float rm = smax[row], ri = sinv[row];                              \
            float p0 = (s0 + 0 <= t) ? __expf(ar[q].x - rm) * ri : 0.f;        \
            float p1 = (s0 + 1 <= t) ? __expf(ar[q].y - rm) * ri : 0.f;        \
            float p2 = (s0 + 2 <= t) ? __expf(ar[q].z - rm) * ri : 0.f;        \
            float p3 = (s0 + 3 <= t) ? __expf(ar[q].w - rm) * ri : 0.f;        \
            *(float4*)&attn[(long)t * T_S + s0] = make_float4(p0, p1, p2, p3); \
            __nv_bfloat16 h0, h1, h2, h3, l0, l1, l2, l3;                      \
            split_bf16(p0, h0, l0); split_bf16(p1, h1, l1);                    \
            split_bf16(p2, h2, l2); split_bf16(p3, h3, l3);                    \
            __nv_bfloat162 ph0, ph1, pl0, pl1;                                 \
            ph0.x = h0; ph0.y = h1; ph1.x = h2; ph1.y = h3;                    \
            pl0.x = l0; pl0.y = l1; pl1.x = l2; pl1.y = l3;                    \
            uint32_t so = row * 80 + seg * 8;                                  \
            *(uint2*)(smc + (bf) * BUFSZ + so) =                               \
                make_uint2(*(uint32_t*)&ph0, *(uint32_t*)&ph1);                \
            *(uint2*)(smc + (bf) * BUFSZ + 10240 + so) =                       \
                make_uint2(*(uint32_t*)&pl0, *(uint32_t*)&pl1);                \
        }                                                                      \
    }

    float4 ar[4];
    PV_LDB(0, 0);
    PV_LDA(0, ar);
    PV_PROC(0, ar, 0);

    for (int c = 0; c < nc; c++) {
        CPWAIT0();
        __syncthreads();
        if (c + 1 < nc) {
            PV_LDB(c + 1, (c + 1) & 1);
            PV_LDA(c + 1, ar);
        }
        uint32_t base = sb + (c & 1) * BUFSZ;
        mma_tile_step2(base, 0, aoff, boff, acc);
        mma_tile_step2(base, 1, aoff, boff, acc);
        if (c + 1 < nc) PV_PROC(c + 1, ar, (c + 1) & 1);
    }
#undef PV_LDB
#undef PV_LDA
#undef PV_PROC

    float* dst;
    if (ngroups == 1) dst = out + ((long)n * T_S + (i << 7)) * D_E;
    else dst = g_part + (((long)(n * 24 + (i - 8)) * 4 + jg) << 14);
#pragma unroll
    for (int mt = 0; mt < 4; mt++)
#pragma unroll
        for (int nt = 0; nt < 4; nt++) {
            int cc = wn + nt * 8 + (lane & 3) * 2;
#pragma unroll
            for (int h = 0; h < 2; h++) {
                int row = wm + mt * 16 + (lane >> 2) + h * 8;
                *(float2*)&dst[(long)row * 128 + cc] =
                    make_float2(acc[mt][nt][h * 2], acc[mt][nt][h * 2 + 1]);
            }
        }
}

// ============================================================
// K5: reduce split-K partials
// ============================================================
__global__ void reduce_kernel(float* __restrict__ out)
{
    int ii = blockIdx.x;
    int n = blockIdx.y;
    int i = ii + 8;
    int ng = (i + 8) >> 3;
    const float* base = g_part + (((long)(n * 24 + ii) * 4) << 14);
    float* o = out + ((long)n * T_S + (i << 7)) * D_E;
    for (int e = threadIdx.x * 4; e < 128 * 128; e += 1024) {
        float4 s = *(const float4*)&base[e];
        for (int g = 1; g < ng; g++) {
            float4 p = *(const float4*)&base[((long)g << 14) + e];
            s.x += p.x; s.y += p.y; s.z += p.z; s.w += p.w;
        }
        *(float4*)&o[e] = s;
    }
}

// ============================================================
extern "C" void kernel_launch(void* const* d_in, const int* in_sizes, int n_in,
                              void* d_out, int out_size)
{
    const float* x  = (const float*)d_in[0];
    const float* Wq = (const float*)d_in[1];
    const float* Wk = (const float*)d_in[2];
    const float* Wv = (const float*)d_in[3];

    const long NTD = (long)NT * D_E;
    const long NTT = (long)N_B * T_S * T_S;

    float* dout = (float*)d_out;
    float* out_ptr;
    float* att_ptr;
    if ((long)out_size >= NTD + NTT) {
        out_ptr = dout;
        att_ptr = dout + NTD;
    } else if ((long)out_size == NTT) {
        att_ptr = dout;
        void* fb = nullptr;
        cudaGetSymbolAddress(&fb, g_out_fallback);
        out_ptr = (float*)fb;
    } else {
        out_ptr = dout;
        att_ptr = dout;
    }

    cudaFuncSetAttribute(qkv_mma_kernel, cudaFuncAttributeMaxDynamicSharedMemorySize, 2 * BUFSZ);
    cudaFuncSetAttribute(scores_mma_kernel, cudaFuncAttributeMaxDynamicSharedMemorySize, 2 * BUFSZ + 4096);
    cudaFuncSetAttribute(pv_mma_kernel, cudaFuncAttributeMaxDynamicSharedMemorySize, 2 * BUFSZ + 1024);

    splitx_kernel<<<(long)NT * DIN / 1024, 256>>>(x);
    wt_kernel<<<dim3(DIN / 32, D_E / 32, 3), 256>>>(Wq, Wk, Wv);

    qkv_mma_kernel<<<dim3(NT / 128, 3), 256, 2 * BUFSZ>>>();

    scores_mma_kernel<<<dim3(1024, N_B), 256, 2 * BUFSZ + 4096>>>(att_ptr);

    pv_mma_kernel<<<dim3(80, N_B), 256, 2 * BUFSZ + 1024>>>(att_ptr, out_ptr);

    reduce_kernel<<<dim3(24, N_B), 256>>>(out_ptr);
}

// round 11
// speedup vs baseline: 4.0033x; 1.0818x over previous
#include <cuda_runtime.h>
#include <cuda_bf16.h>
#include <math.h>
#include <stdint.h>

#define N_B 4
#define T_S 4096
#define DIN 1024
#define D_E 128
#define NT (N_B * T_S)
#define PCH 40      // smem row pitch in halfs (32 + 8 pad)
#define BUFSZ 40960 // one stage: 4 regions x 10240B

// ---- scratch (device globals: allocation-free) ----
__device__ __nv_bfloat16 g_xh[(long)NT * DIN];
__device__ __nv_bfloat16 g_xl[(long)NT * DIN];
__device__ __nv_bfloat16 g_wth[3 * D_E * DIN];
__device__ __nv_bfloat16 g_wtl[3 * D_E * DIN];
__device__ __nv_bfloat16 g_qh[NT * D_E];
__device__ __nv_bfloat16 g_ql[NT * D_E];
__device__ __nv_bfloat16 g_kh[NT * D_E];
__device__ __nv_bfloat16 g_kl[NT * D_E];
__device__ __nv_bfloat16 g_vth[(long)N_B * D_E * T_S];
__device__ __nv_bfloat16 g_vtl[(long)N_B * D_E * T_S];
__device__ float g_pmax[(long)NT * 32];
__device__ float g_psum[(long)NT * 32];
__device__ float g_part[(long)4 * 24 * 4 * 128 * 128];
__device__ float g_out_fallback[NT * D_E];

__device__ __forceinline__ float neg_inf() { return __int_as_float(0xff800000); }

__device__ __forceinline__ uint32_t smem_u32(const void* p) {
    uint32_t a;
    asm("{ .reg .u64 t; cvta.to.shared.u64 t, %1; cvt.u32.u64 %0, t; }" : "=r"(a) : "l"(p));
    return a;
}
__device__ __forceinline__ void split_bf16(float x, __nv_bfloat16& h, __nv_bfloat16& l) {
    h = __float2bfloat16(x);
    l = __float2bfloat16(x - __bfloat162float(h));
}

#define CP16(dst, src) asm volatile("cp.async.cg.shared.global [%0], [%1], 16;" :: "r"(dst), "l"(src))
#define CPCOMMIT() asm volatile("cp.async.commit_group;" ::: "memory")
#define CPWAIT0() asm volatile("cp.async.wait_group 0;" ::: "memory")

__device__ __forceinline__ void ldsm_x4(uint32_t* r, uint32_t addr) {
    asm volatile("ldmatrix.sync.aligned.m8n8.x4.shared.b16 {%0,%1,%2,%3}, [%4];"
        : "=r"(r[0]), "=r"(r[1]), "=r"(r[2]), "=r"(r[3]) : "r"(addr));
}
__device__ __forceinline__ void ldsm_x2(uint32_t* r, uint32_t addr) {
    asm volatile("ldmatrix.sync.aligned.m8n8.x2.shared.b16 {%0,%1}, [%2];"
        : "=r"(r[0]), "=r"(r[1]) : "r"(addr));
}
__device__ __forceinline__ void mma_bf16(float* c, const uint32_t* a, const uint32_t* b) {
    asm volatile(
        "mma.sync.aligned.m16n8k16.row.col.f32.bf16.bf16.f32 "
        "{%0,%1,%2,%3}, {%4,%5,%6,%7}, {%8,%9}, {%0,%1,%2,%3};"
        : "+f"(c[0]), "+f"(c[1]), "+f"(c[2]), "+f"(c[3])
        : "r"(a[0]), "r"(a[1]), "r"(a[2]), "r"(a[3]), "r"(b[0]), "r"(b[1]));
}

// One k16 step, mt-serial, hoisted per-warp addresses.
// Region layout within a stage: Ah@0, Al@10240, Bh@20480, Bl@30720.
__device__ __forceinline__ void mma_tile_step2(uint32_t base, int ks,
                                               uint32_t aoff, uint32_t boff,
                                               float (*acc)[4][4])
{
    uint32_t ko = (uint32_t)ks * 32;
    uint32_t bh[4][2], bl[4][2];
#pragma unroll
    for (int nt = 0; nt < 4; nt++) {
        uint32_t ro = boff + nt * (8 * 80) + ko;
        ldsm_x2(bh[nt], base + 20480 + ro);
        ldsm_x2(bl[nt], base + 30720 + ro);
    }
#pragma unroll
    for (int mt = 0; mt < 4; mt++) {
        uint32_t ah[4], al[4];
        uint32_t ro = aoff + mt * (16 * 80) + ko;
        ldsm_x4(ah, base + ro);
        ldsm_x4(al, base + 10240 + ro);
#pragma unroll
        for (int nt = 0; nt < 4; nt++) {
            mma_bf16(acc[mt][nt], ah, bh[nt]);
            mma_bf16(acc[mt][nt], ah, bl[nt]);
            mma_bf16(acc[mt][nt], al, bh[nt]);
        }
    }
}

// ============================================================
// K-1: split x into bf16 hi/lo
// ============================================================
__global__ __launch_bounds__(256) void splitx_kernel(const float* __restrict__ x)
{
    long idx = ((long)blockIdx.x * 256 + threadIdx.x) * 4;
    float4 a = *(const float4*)&x[idx];
    __nv_bfloat16 h0, h1, h2, h3, l0, l1, l2, l3;
    split_bf16(a.x, h0, l0);
    split_bf16(a.y, h1, l1);
    split_bf16(a.z, h2, l2);
    split_bf16(a.w, h3, l3);
    __nv_bfloat162 ph0, ph1, pl0, pl1;
    ph0.x = h0; ph0.y = h1; ph1.x = h2; ph1.y = h3;
    pl0.x = l0; pl0.y = l1; pl1.x = l2; pl1.y = l3;
    *(uint2*)&g_xh[idx] = make_uint2(*(uint32_t*)&ph0, *(uint32_t*)&ph1);
    *(uint2*)&g_xl[idx] = make_uint2(*(uint32_t*)&pl0, *(uint32_t*)&pl1);
}

// ============================================================
// K0: transpose + split W
// ============================================================
__global__ __launch_bounds__(256) void wt_kernel(const float* __restrict__ Wq,
                                                 const float* __restrict__ Wk,
                                                 const float* __restrict__ Wv)
{
    const float* W = (blockIdx.z == 0) ? Wq : ((blockIdx.z == 1) ? Wk : Wv);
    __shared__ float t[32][33];
    int tid = threadIdx.x;
    int tx = tid & 31, ty = tid >> 5;
    int k0 = blockIdx.x * 32, n0 = blockIdx.y * 32;
#pragma unroll
    for (int s = 0; s < 4; s++) t[ty + s * 8][tx] = W[(k0 + ty + s * 8) * D_E + n0 + tx];
    __syncthreads();
    long wb = (long)blockIdx.z * D_E * DIN;
#pragma unroll
    for (int s = 0; s < 4; s++) {
        int n = n0 + ty + s * 8, k = k0 + tx;
        __nv_bfloat16 h, l;
        split_bf16(t[tx][ty + s * 8], h, l);
        g_wth[wb + (long)n * DIN + k] = h;
        g_wtl[wb + (long)n * DIN + k] = l;
    }
}

// ============================================================
// K1: QKV via mma.sync, 2-stage, 2 CTAs/SM. grid (3, NT/128):
// the 3 w-blocks of a tile are adjacent -> x tile served from L2.
// ============================================================
__global__ __launch_bounds__(256, 2) void qkv_mma_kernel()
{
    extern __shared__ char smc[];
    uint32_t sb = smem_u32(smc);
    int tid = threadIdx.x, lane = tid & 31, wid = tid >> 5;
    int w = blockIdx.x;
    long mBase = (long)blockIdx.y * 128;

    const __nv_bfloat16* sAh = g_xh + mBase * DIN;
    const __nv_bfloat16* sAl = g_xl + mBase * DIN;
    const __nv_bfloat16* sBh = g_wth + (long)w * D_E * DIN;
    const __nv_bfloat16* sBl = g_wtl + (long)w * D_E * DIN;

    int wm = (wid >> 2) * 64, wn = (wid & 3) * 32;
    uint32_t aoff = (uint32_t)(wm + (lane & 15)) * 80 + (lane >> 4) * 16;
    uint32_t boff = (uint32_t)(wn + (lane & 7)) * 80 + ((lane >> 3) & 1) * 16;

    float acc[4][4][4];
#pragma unroll
    for (int a = 0; a < 4; a++)
#pragma unroll
        for (int b = 0; b < 4; b++)
#pragma unroll
            for (int cc = 0; cc < 4; cc++) acc[a][b][cc] = 0.f;

#define QKV_LOAD(c, bf)                                                        \
    {                                                                          \
        int k0_ = (c) * 32;                                                    \
        uint32_t db_ = sb + (bf) * BUFSZ;                                      \
        for (int u = tid; u < 2048; u += 256) {                                \
            int arr = u >> 9, idx = u & 511, row = idx >> 2, seg = idx & 3;    \
            const __nv_bfloat16* s =                                           \
                (arr == 0) ? sAh : (arr == 1) ? sAl : (arr == 2) ? sBh : sBl;  \
            CP16(db_ + arr * 10240 + row * 80 + seg * 16,                      \
                 s + (long)row * DIN + k0_ + seg * 8);                         \
        }                                                                      \
        CPCOMMIT();                                                            \
    }

    QKV_LOAD(0, 0);
    for (int c = 0; c < 32; c++) {
        CPWAIT0();
        __syncthreads();
        if (c + 1 < 32) QKV_LOAD(c + 1, (c + 1) & 1);
        uint32_t base = sb + (c & 1) * BUFSZ;
        mma_tile_step2(base, 0, aoff, boff, acc);
        mma_tile_step2(base, 1, aoff, boff, acc);
    }
#undef QKV_LOAD
    __syncthreads();

    if (w < 2) {
        __nv_bfloat16* dh = w ? g_kh : g_qh;
        __nv_bfloat16* dl = w ? g_kl : g_ql;
#pragma unroll
        for (int mt = 0; mt < 4; mt++)
#pragma unroll
            for (int nt = 0; nt < 4; nt++) {
                int cc = wn + nt * 8 + (lane & 3) * 2;
#pragma unroll
                for (int h = 0; h < 2; h++) {
                    int row = wm + mt * 16 + (lane >> 2) + h * 8;
                    float v0 = acc[mt][nt][h * 2], v1 = acc[mt][nt][h * 2 + 1];
                    __nv_bfloat16 h0, h1, l0, l1;
                    split_bf16(v0, h0, l0);
                    split_bf16(v1, h1, l1);
                    __nv_bfloat162 ph, pl;
                    ph.x = h0; ph.y = h1; pl.x = l0; pl.y = l1;
                    long o = (mBase + row) * D_E + cc;
                    *(__nv_bfloat162*)&dh[o] = ph;
                    *(__nv_bfloat162*)&dl[o] = pl;
                }
            }
    } else {
        float* stage = (float*)smc;  // 128 x 129 f32 = 66048B < 2*BUFSZ
#pragma unroll
        for (int mt = 0; mt < 4; mt++)
#pragma unroll
            for (int nt = 0; nt < 4; nt++) {
                int cc = wn + nt * 8 + (lane & 3) * 2;
#pragma unroll
                for (int h = 0; h < 2; h++) {
                    int row = wm + mt * 16 + (lane >> 2) + h * 8;
                    stage[row * 129 + cc] = acc[mt][nt][h * 2];
                    stage[row * 129 + cc + 1] = acc[mt][nt][h * 2 + 1];
                }
            }
        __syncthreads();
        int nb = (int)(mBase >> 12);
        int tb = (int)(mBase & (T_S - 1));
        for (int u = tid; u < 8192; u += 256) {
            int d = u >> 6, tp = (u & 63) * 2;
            float v0 = stage[tp * 129 + d];
            float v1 = stage[(tp + 1) * 129 + d];
            __nv_bfloat16 h0, h1, l0, l1;
            split_bf16(v0, h0, l0);
            split_bf16(v1, h1, l1);
            __nv_bfloat162 ph, pl;
            ph.x = h0; ph.y = h1; pl.x = l0; pl.y = l1;
            long o = ((long)nb * D_E + d) * T_S + tb + tp;
            *(__nv_bfloat162*)&g_vth[o] = ph;
            *(__nv_bfloat162*)&g_vtl[o] = pl;
        }
    }
}

// ============================================================
// K2: scores. Full 32x32 tile grid: j>i tiles zero-fill att.
// j<=i tiles: S = Q K^T; att stores u = exp(logit - M_tile),
// M_tile = per-row max over the whole 128-col tile (3-phase epilogue).
// ============================================================
__global__ __launch_bounds__(256, 2) void scores_mma_kernel(float* __restrict__ att)
{
    int i = blockIdx.x >> 5;
    int j = blockIdx.x & 31;
    int n = blockIdx.y;
    float* attn = att + (long)n * T_S * T_S;

    int tid = threadIdx.x;

    if (j > i) {
        float4 z = make_float4(0.f, 0.f, 0.f, 0.f);
        float* tp = attn + (long)(i * 128) * T_S + j * 128;
#pragma unroll 4
        for (int u = tid; u < 4096; u += 256) {
            int row = u >> 5, c4 = u & 31;
            *(float4*)&tp[(long)row * T_S + c4 * 4] = z;
        }
        return;
    }

    extern __shared__ char smc[];
    uint32_t sb = smem_u32(smc);
    int lane = tid & 31, wid = tid >> 5;

    const __nv_bfloat16* sAh = g_qh + ((long)n * T_S + i * 128) * D_E;
    const __nv_bfloat16* sAl = g_ql + ((long)n * T_S + i * 128) * D_E;
    const __nv_bfloat16* sBh = g_kh + ((long)n * T_S + j * 128) * D_E;
    const __nv_bfloat16* sBl = g_kl + ((long)n * T_S + j * 128) * D_E;

    int wm = (wid >> 2) * 64, wn = (wid & 3) * 32;
    uint32_t aoff = (uint32_t)(wm + (lane & 15)) * 80 + (lane >> 4) * 16;
    uint32_t boff = (uint32_t)(wn + (lane & 7)) * 80 + ((lane >> 3) & 1) * 16;

    float acc[4][4][4];
#pragma unroll
    for (int a = 0; a < 4; a++)
#pragma unroll
        for (int b = 0; b < 4; b++)
#pragma unroll
            for (int cc = 0; cc < 4; cc++) acc[a][b][cc] = 0.f;

#define SC_LOAD(c, bf)                                                         \
    {                                                                          \
        int k0_ = (c) * 32;                                                    \
        uint32_t db_ = sb + (bf) * BUFSZ;                                      \
        for (int u = tid; u < 2048; u += 256) {                                \
            int arr = u >> 9, idx = u & 511, row = idx >> 2, seg = idx & 3;    \
            const __nv_bfloat16* s =                                           \
                (arr == 0) ? sAh : (arr == 1) ? sAl : (arr == 2) ? sBh : sBl;  \
            CP16(db_ + arr * 10240 + row * 80 + seg * 16,                      \
                 s + (long)row * D_E + k0_ + seg * 8);                         \
        }                                                                      \
        CPCOMMIT();                                                            \
    }

    SC_LOAD(0, 0);
    for (int c = 0; c < 4; c++) {
        CPWAIT0();
        __syncthreads();
        if (c + 1 < 4) SC_LOAD(c + 1, (c + 1) & 1);
        uint32_t base = sb + (c & 1) * BUFSZ;
        mma_tile_step2(base, 0, aoff, boff, acc);
        mma_tile_step2(base, 1, aoff, boff, acc);
    }
#undef SC_LOAD

    // ---- 3-phase epilogue: group max -> tile max -> write u + sums
    float* pm = (float*)(smc + 2 * BUFSZ);  // [128][4] group maxes
    float* ps = pm + 512;                   // [128][4] group sums
    float* sM = ps + 512;                   // [128] tile max per row
    float NI = neg_inf();

    __syncthreads();
    // phase 1: per-warp (32-col group) maxes
#pragma unroll
    for (int mt = 0; mt < 4; mt++)
#pragma unroll
        for (int h = 0; h < 2; h++) {
            int row = wm + mt * 16 + (lane >> 2) + h * 8;
            int tg = i * 128 + row;
            float m = NI;
#pragma unroll
            for (int nt = 0; nt < 4; nt++)
#pragma unroll
                for (int e = 0; e < 2; e++) {
                    int s = j * 128 + wn + nt * 8 + (lane & 3) * 2 + e;
                    if (s <= tg) {
                        float v = acc[mt][nt][h * 2 + e];
                        float ev = (v == 0.0f) ? NI : v;
                        m = fmaxf(m, ev);
                    }
                }
            m = fmaxf(m, __shfl_xor_sync(0xffffffffu, m, 1));
            m = fmaxf(m, __shfl_xor_sync(0xffffffffu, m, 2));
            if ((lane & 3) == 0) pm[row * 4 + (wid & 3)] = m;
        }
    __syncthreads();

    // phase 2: tile max per row
    if (tid < 128) {
        float m0 = pm[tid * 4], m1 = pm[tid * 4 + 1], m2 = pm[tid * 4 + 2], m3 = pm[tid * 4 + 3];
        sM[tid] = fmaxf(fmaxf(m0, m1), fmaxf(m2, m3));
    }
    __syncthreads();

    // phase 3: write u = exp(v - M_tile), per-group sums
#pragma unroll
    for (int mt = 0; mt < 4; mt++)
#pragma unroll
        for (int h = 0; h < 2; h++) {
            int row = wm + mt * 16 + (lane >> 2) + h * 8;
            int tg = i * 128 + row;
            float M = sM[row];
            float ssum = 0.f;
            if (M != NI) {
#pragma unroll
                for (int nt = 0; nt < 4; nt++)
#pragma unroll
                    for (int e = 0; e < 2; e++) {
                        int s = j * 128 + wn + nt * 8 + (lane & 3) * 2 + e;
                        if (s <= tg) {
                            float v = acc[mt][nt][h * 2 + e];
                            float u = (v == 0.0f) ? 0.f : __expf(v - M);
                            attn[(long)tg * T_S + s] = u;
                            ssum += u;
                        }
                    }
            } else {
#pragma unroll
                for (int nt = 0; nt < 4; nt++)
#pragma unroll
                    for (int e = 0; e < 2; e++) {
                        int s = j * 128 + wn + nt * 8 + (lane & 3) * 2 + e;
                        if (s <= tg) attn[(long)tg * T_S + s] = 0.f;
                    }
            }
            ssum += __shfl_xor_sync(0xffffffffu, ssum, 1);
            ssum += __shfl_xor_sync(0xffffffffu, ssum, 2);
            if ((lane & 3) == 0) ps[row * 4 + (wid & 3)] = ssum;
        }
    __syncthreads();

    if (tid < 128) {
        float S = ps[tid * 4] + ps[tid * 4 + 1] + ps[tid * 4 + 2] + ps[tid * 4 + 3];
        long o = ((long)n * T_S + i * 128 + tid) * 32 + j;
        g_pmax[o] = sM[tid];
        g_psum[o] = S;
    }
}

// ============================================================
// K4: split-K PV. att holds u = exp(logit - m_tile); p = u * f,
// f[row][jtile] = exp(m_j - M)/S precomputed in smem (16KB).
// grid (80, N_B), 2 CTAs/SM.
// ============================================================
__global__ __launch_bounds__(256, 2) void pv_mma_kernel(float* __restrict__ att,
                                                        float* __restrict__ out)
{
    int b = blockIdx.x;
    int n = blockIdx.y;
    int i = 31, jg = 0;
    for (i = 31; i >= 0; --i) {
        int g = (i + 8) >> 3;
        if (b < g) { jg = b; break; }
        b -= g;
    }
    int ngroups = (i + 8) >> 3;
    int kStart = jg << 10;
    int kEndA = min((jg + 1) << 10, (i + 1) << 7);
    int nc = (kEndA - kStart) >> 5;

    extern __shared__ char smc[];
    uint32_t sb = smem_u32(smc);
    float* sf = (float*)(smc + 2 * BUFSZ);  // [128][32] = 16KB
    int tid = threadIdx.x, lane = tid & 31, wid = tid >> 5;

    float* attn = att + (long)n * T_S * T_S;

    // combine per-tile softmax partials -> per (row, jtile) factor
    if (tid < 128) {
        long r = (long)n * T_S + (i << 7) + tid;
        const float* pmr = g_pmax + r * 32;
        const float* psr = g_psum + r * 32;
        float NI = neg_inf();
        float M = NI;
        for (int jj = 0; jj <= i; jj++) M = fmaxf(M, pmr[jj]);
        float S = 0.f;
        for (int jj = 0; jj <= i; jj++) {
            float mj = pmr[jj];
            if (mj != NI) S += psr[jj] * __expf(mj - M);
        }
        float inv = 1.f / S;
        for (int jj = 0; jj <= i; jj++) {
            float mj = pmr[jj];
            sf[tid * 32 + jj] = (mj != NI) ? __expf(mj - M) * inv : 0.f;
        }
    }
    __syncthreads();

    int wm = (wid >> 2) * 64, wn = (wid & 3) * 32;
    uint32_t aoff = (uint32_t)(wm + (lane & 15)) * 80 + (lane >> 4) * 16;
    uint32_t boff = (uint32_t)(wn + (lane & 7)) * 80 + ((lane >> 3) & 1) * 16;

    float acc[4][4][4];
#pragma unroll
    for (int a = 0; a < 4; a++)
#pragma unroll
        for (int b2 = 0; b2 < 4; b2++)
#pragma unroll
            for (int cc = 0; cc < 4; cc++) acc[a][b2][cc] = 0.f;

#define PV_LDB(c, bf)                                                          \
    {                                                                          \
        int k0_ = kStart + (c) * 32;                                           \
        uint32_t db_ = sb + (bf) * BUFSZ + 20480;                              \
        for (int u = tid; u < 1024; u += 256) {                                \
            int arr = u >> 9, idx = u & 511, row = idx >> 2, seg = idx & 3;    \
            const __nv_bfloat16* s = (arr ? g_vtl : g_vth) +                   \
                ((long)n * D_E + row) * T_S + k0_ + seg * 8;                   \
            CP16(db_ + arr * 10240 + row * 80 + seg * 16, s);                  \
        }                                                                      \
        CPCOMMIT();                                                            \
    }

#define PV_LDA(c, ar)                                                          \
    {                                                                          \
        int k0_ = kStart + (c) * 32;                                           \
        _Pragma("unroll") for (int q = 0; q < 4; q++) {                        \
            int idx = tid + q * 256;                                           \
            int row = idx >> 3, seg = idx & 7;                                 \
            ar[q] = *(const float4*)&attn[(long)((i << 7) + row) * T_S + k0_ + seg * 4]; \
        }                                                                      \
    }

#define PV_PROC(c, ar, bf)                                                     \
    {                                                                          \
        int k0_ = kStart + (c) * 32;                                           \
        int jt_ = k0_ >> 7;                                                    \
        _Pragma("unroll") for (int q = 0; q < 4; q++) {                        \
            int idx = tid + q * 256;                                           \
            int row = idx >> 3, seg = idx & 7;                                 \
            int t = (i << 7) + row;                                            \
            int s0 = k0_ + seg * 4;                                            \
            float f = sf[row * 32 + jt_];                                      \
            float p0 = (s0 + 0 <= t) ? ar[q].x * f : 0.f;                      \
            float p1 = (s0 + 1 <= t) ? ar[q].y * f : 0.f;                      \
            float p2 = (s0 + 2 <= t) ? ar[q].z * f : 0.f;                      \
            float p3 = (s0 + 3 <= t) ? ar[q].w * f : 0.f;                      \
            *(float4*)&attn[(long)t * T_S + s0] = make_float4(p0, p1, p2, p3); \
            __nv_bfloat16 h0, h1, h2, h3, l0, l1, l2, l3;                      \
            split_bf16(p0, h0, l0); split_bf16(p1, h1, l1);                    \
            split_bf16(p2, h2, l2); split_bf16(p3, h3, l3);                    \
            __nv_bfloat162 ph0, ph1, pl0, pl1;                                 \
            ph0.x = h0; ph0.y = h1; ph1.x = h2; ph1.y = h3;                    \
            pl0.x = l0; pl0.y = l1; pl1.x = l2; pl1.y = l3;                    \
            uint32_t so = row * 80 + seg * 8;                                  \
            *(uint2*)(smc + (bf) * BUFSZ + so) =                               \
                make_uint2(*(uint32_t*)&ph0, *(uint32_t*)&ph1);                \
            *(uint2*)(smc + (bf) * BUFSZ + 10240 + so) =                       \
                make_uint2(*(uint32_t*)&pl0, *(uint32_t*)&pl1);                \
        }                                                                      \
    }

    float4 ar[4];
    PV_LDB(0, 0);
    PV_LDA(0, ar);
    PV_PROC(0, ar, 0);

    for (int c = 0; c < nc; c++) {
        CPWAIT0();
        __syncthreads();
        if (c + 1 < nc) {
            PV_LDB(c + 1, (c + 1) & 1);
            PV_LDA(c + 1, ar);
        }
        uint32_t base = sb + (c & 1) * BUFSZ;
        mma_tile_step2(base, 0, aoff, boff, acc);
        mma_tile_step2(base, 1, aoff, boff, acc);
        if (c + 1 < nc) PV_PROC(c + 1, ar, (c + 1) & 1);
    }
#undef PV_LDB
#undef PV_LDA
#undef PV_PROC

    float* dst;
    if (ngroups == 1) dst = out + ((long)n * T_S + (i << 7)) * D_E;
    else dst = g_part + (((long)(n * 24 + (i - 8)) * 4 + jg) << 14);
#pragma unroll
    for (int mt = 0; mt < 4; mt++)
#pragma unroll
        for (int nt = 0; nt < 4; nt++) {
            int cc = wn + nt * 8 + (lane & 3) * 2;
#pragma unroll
            for (int h = 0; h < 2; h++) {
                int row = wm + mt * 16 + (lane >> 2) + h * 8;
                *(float2*)&dst[(long)row * 128 + cc] =
                    make_float2(acc[mt][nt][h * 2], acc[mt][nt][h * 2 + 1]);
            }
        }
}

// ============================================================
// K5: reduce split-K partials
// ============================================================
__global__ void reduce_kernel(float* __restrict__ out)
{
    int ii = blockIdx.x;
    int n = blockIdx.y;
    int i = ii + 8;
    int ng = (i + 8) >> 3;
    const float* base = g_part + (((long)(n * 24 + ii) * 4) << 14);
    float* o = out + ((long)n * T_S + (i << 7)) * D_E;
    for (int e = threadIdx.x * 4; e < 128 * 128; e += 1024) {
        float4 s = *(const float4*)&base[e];
        for (int g = 1; g < ng; g++) {
            float4 p = *(const float4*)&base[((long)g << 14) + e];
            s.x += p.x; s.y += p.y; s.z += p.z; s.w += p.w;
        }
        *(float4*)&o[e] = s;
    }
}

// ============================================================
extern "C" void kernel_launch(void* const* d_in, const int* in_sizes, int n_in,
                              void* d_out, int out_size)
{
    const float* x  = (const float*)d_in[0];
    const float* Wq = (const float*)d_in[1];
    const float* Wk = (const float*)d_in[2];
    const float* Wv = (const float*)d_in[3];

    const long NTD = (long)NT * D_E;
    const long NTT = (long)N_B * T_S * T_S;

    float* dout = (float*)d_out;
    float* out_ptr;
    float* att_ptr;
    if ((long)out_size >= NTD + NTT) {
        out_ptr = dout;
        att_ptr = dout + NTD;
    } else if ((long)out_size == NTT) {
        att_ptr = dout;
        void* fb = nullptr;
        cudaGetSymbolAddress(&fb, g_out_fallback);
        out_ptr = (float*)fb;
    } else {
        out_ptr = dout;
        att_ptr = dout;
    }

    cudaFuncSetAttribute(qkv_mma_kernel, cudaFuncAttributeMaxDynamicSharedMemorySize, 2 * BUFSZ);
    cudaFuncSetAttribute(scores_mma_kernel, cudaFuncAttributeMaxDynamicSharedMemorySize, 2 * BUFSZ + 8192);
    cudaFuncSetAttribute(pv_mma_kernel, cudaFuncAttributeMaxDynamicSharedMemorySize, 2 * BUFSZ + 16384);

    splitx_kernel<<<(long)NT * DIN / 1024, 256>>>(x);
    wt_kernel<<<dim3(DIN / 32, D_E / 32, 3), 256>>>(Wq, Wk, Wv);

    qkv_mma_kernel<<<dim3(3, NT / 128), 256, 2 * BUFSZ>>>();

    scores_mma_kernel<<<dim3(1024, N_B), 256, 2 * BUFSZ + 8192>>>(att_ptr);

    pv_mma_kernel<<<dim3(80, N_B), 256, 2 * BUFSZ + 16384>>>(att_ptr, out_ptr);

    reduce_kernel<<<dim3(24, N_B), 256>>>(out_ptr);
}